// round 3
// baseline (speedup 1.0000x reference)
#include <cuda_runtime.h>
#include <math.h>

#define MAXN 100000
#define MAXE 3200000

// ---------------- device scratch (no allocations allowed) ----------------
__device__ float g_h1[MAXN * 128];
__device__ float g_h2[MAXN * 64];
__device__ float g_hw[MAXN * 64];
__device__ float g_agg[MAXN * 64];
__device__ float g_hw2[MAXN * 32];
__device__ float g_agg2[MAXN * 32];
__device__ int   g_indeg[MAXN];
__device__ float g_dinv[MAXN];
__device__ int   g_rowptr[MAXN + 1];
__device__ int   g_cursor[MAXN];
__device__ int   g_csrc[MAXE];
__device__ float g_csrw[MAXE];
__device__ float g_sum[128];
__device__ float g_sq[128];
__device__ float g_scale[128];
__device__ float g_shift[128];
__device__ int   g_bsums[256];

// ---------------- tiled fp32 GEMM: C[M,BN] = A[M,K] @ B[K,BN] -------------
// BM=128, BK=16, 8x8 per-thread tile, double-buffered shared.
template <int BN>
__global__ void __launch_bounds__((BN / 8) * 16)
gemm_tiled(const float* __restrict__ A, const float* __restrict__ B,
           float* __restrict__ C, int M, int K) {
    constexpr int BM = 128, BK = 16;
    constexpr int TX = BN / 8;
    constexpr int T  = TX * 16;
    constexpr int A4 = BM * BK / 4;   // float4s per A tile
    constexpr int B4 = BK * BN / 4;   // float4s per B tile
    constexpr int APT = A4 / T;
    constexpr int BPT = B4 / T;

    __shared__ float As[2][BK][BM];
    __shared__ float Bs[2][BK][BN];

    const int tid = threadIdx.x;
    const int tx = tid % TX, ty = tid / TX;
    const int m0 = blockIdx.x * BM;

    float acc[8][8];
#pragma unroll
    for (int i = 0; i < 8; i++)
#pragma unroll
        for (int j = 0; j < 8; j++) acc[i][j] = 0.f;

    float4 ra[APT], rb[BPT];

    auto ldg_tile = [&](int kt) {
        int k0 = kt * BK;
#pragma unroll
        for (int i = 0; i < APT; i++) {
            int f = tid + i * T;
            int m = f >> 2;          // f / (BK/4)
            int kq = f & 3;
            if (m0 + m < M)
                ra[i] = *(const float4*)(A + (size_t)(m0 + m) * K + k0 + kq * 4);
            else
                ra[i] = make_float4(0.f, 0.f, 0.f, 0.f);
        }
#pragma unroll
        for (int i = 0; i < BPT; i++) {
            int f = tid + i * T;
            int k = f / (BN / 4);
            int nq = f % (BN / 4);
            rb[i] = *(const float4*)(B + (size_t)(k0 + k) * BN + nq * 4);
        }
    };
    auto sts_tile = [&](int buf) {
#pragma unroll
        for (int i = 0; i < APT; i++) {
            int f = tid + i * T;
            int m = f >> 2;
            int kq = f & 3;
            As[buf][kq * 4 + 0][m] = ra[i].x;
            As[buf][kq * 4 + 1][m] = ra[i].y;
            As[buf][kq * 4 + 2][m] = ra[i].z;
            As[buf][kq * 4 + 3][m] = ra[i].w;
        }
#pragma unroll
        for (int i = 0; i < BPT; i++) {
            int f = tid + i * T;
            int k = f / (BN / 4);
            int nq = f % (BN / 4);
            *(float4*)&Bs[buf][k][nq * 4] = rb[i];
        }
    };

    const int nt = K / BK;
    ldg_tile(0);
    sts_tile(0);
    __syncthreads();

    for (int t = 0; t < nt; ++t) {
        int cur = t & 1;
        if (t + 1 < nt) ldg_tile(t + 1);
#pragma unroll
        for (int kk = 0; kk < BK; ++kk) {
            float4 a0 = *(const float4*)&As[cur][kk][ty * 8];
            float4 a1 = *(const float4*)&As[cur][kk][ty * 8 + 4];
            float4 b0 = *(const float4*)&Bs[cur][kk][tx * 8];
            float4 b1 = *(const float4*)&Bs[cur][kk][tx * 8 + 4];
            float av[8] = {a0.x, a0.y, a0.z, a0.w, a1.x, a1.y, a1.z, a1.w};
            float bv[8] = {b0.x, b0.y, b0.z, b0.w, b1.x, b1.y, b1.z, b1.w};
#pragma unroll
            for (int i = 0; i < 8; i++)
#pragma unroll
                for (int j = 0; j < 8; j++) acc[i][j] += av[i] * bv[j];
        }
        if (t + 1 < nt) sts_tile((t + 1) & 1);
        __syncthreads();
    }

#pragma unroll
    for (int i = 0; i < 8; i++) {
        int m = m0 + ty * 8 + i;
        if (m < M) {
            *(float4*)(C + (size_t)m * BN + tx * 8) =
                make_float4(acc[i][0], acc[i][1], acc[i][2], acc[i][3]);
            *(float4*)(C + (size_t)m * BN + tx * 8 + 4) =
                make_float4(acc[i][4], acc[i][5], acc[i][6], acc[i][7]);
        }
    }
}

// ---------------- BatchNorm (training mode, batch stats) ------------------
__global__ void zero_stats_kernel() {
    if (threadIdx.x < 128) { g_sum[threadIdx.x] = 0.f; g_sq[threadIdx.x] = 0.f; }
}

template <int C>
__global__ void colstats_kernel(const float* __restrict__ h, int M) {
    int gtid = blockIdx.x * blockDim.x + threadIdx.x;
    int c = gtid & (C - 1);
    int r0 = gtid / C;
    int stride = (gridDim.x * blockDim.x) / C;
    float s = 0.f, q = 0.f;
    for (int r = r0; r < M; r += stride) {
        float v = h[(size_t)r * C + c];
        s += v;
        q += v * v;
    }
    atomicAdd(&g_sum[c], s);
    atomicAdd(&g_sq[c], q);
}

__global__ void bn_finalize_kernel(const float* __restrict__ gamma,
                                   const float* __restrict__ beta,
                                   int C, float invM, float eps) {
    int c = threadIdx.x;
    if (c < C) {
        float mean = g_sum[c] * invM;
        float var = g_sq[c] * invM - mean * mean;
        float sc = gamma[c] * rsqrtf(var + eps);
        g_scale[c] = sc;
        g_shift[c] = beta[c] - mean * sc;
    }
}

// ACT: 0 = identity, 1 = ELU, 2 = ReLU
template <int C, int ACT>
__global__ void bn_apply_kernel(const float* __restrict__ in,
                                float* __restrict__ out, int M) {
    int total4 = M * C / 4;
    for (int idx = blockIdx.x * blockDim.x + threadIdx.x; idx < total4;
         idx += gridDim.x * blockDim.x) {
        float4 v = ((const float4*)in)[idx];
        int c = (idx * 4) & (C - 1);
        float r[4] = {v.x, v.y, v.z, v.w};
#pragma unroll
        for (int j = 0; j < 4; j++) {
            float t = r[j] * g_scale[c + j] + g_shift[c + j];
            if (ACT == 1) t = (t > 0.f) ? t : expm1f(t);
            else if (ACT == 2) t = (t > 0.f) ? t : 0.f;
            r[j] = t;
        }
        ((float4*)out)[idx] = make_float4(r[0], r[1], r[2], r[3]);
    }
}

// ---------------- graph structure: degrees + CSR build --------------------
__global__ void zero_indeg_kernel(int N) {
    int i = blockIdx.x * blockDim.x + threadIdx.x;
    if (i < N) g_indeg[i] = 0;
}
__global__ void count_kernel(const int* __restrict__ ei, int E) {
    int e = blockIdx.x * blockDim.x + threadIdx.x;
    if (e < E) atomicAdd(&g_indeg[ei[E + e]], 1);
}
__global__ void dinv_kernel(int N) {
    int i = blockIdx.x * blockDim.x + threadIdx.x;
    if (i < N) g_dinv[i] = rsqrtf((float)(g_indeg[i] + 1));  // +1 self loop
}
__global__ void scan1_kernel(int N) {
    __shared__ int sh[1024];
    int tid = threadIdx.x;
    int i = blockIdx.x * 1024 + tid;
    int v = (i < N) ? g_indeg[i] : 0;
    sh[tid] = v;
    __syncthreads();
    for (int off = 1; off < 1024; off <<= 1) {
        int t = (tid >= off) ? sh[tid - off] : 0;
        __syncthreads();
        sh[tid] += t;
        __syncthreads();
    }
    if (i < N) g_rowptr[i] = sh[tid] - v;  // block-local exclusive
    if (tid == 1023) g_bsums[blockIdx.x] = sh[1023];
}
__global__ void scan2_kernel(int nb) {
    __shared__ int sh[256];
    int tid = threadIdx.x;
    int v = (tid < nb) ? g_bsums[tid] : 0;
    sh[tid] = v;
    __syncthreads();
    for (int off = 1; off < 256; off <<= 1) {
        int t = (tid >= off) ? sh[tid - off] : 0;
        __syncthreads();
        sh[tid] += t;
        __syncthreads();
    }
    if (tid < nb) g_bsums[tid] = sh[tid] - v;  // exclusive block offsets
}
__global__ void scan3_kernel(int N, int E) {
    int i = blockIdx.x * blockDim.x + threadIdx.x;
    if (i < N) {
        int v = g_rowptr[i] + g_bsums[i >> 10];
        g_rowptr[i] = v;
        g_cursor[i] = v;
    }
    if (i == 0) g_rowptr[N] = E;
}
__global__ void fill_kernel(const int* __restrict__ ei, int E) {
    int e = blockIdx.x * blockDim.x + threadIdx.x;
    if (e < E) {
        int s = ei[e], d = ei[E + e];
        int p = atomicAdd(&g_cursor[d], 1);
        g_csrc[p] = s;
        g_csrw[p] = g_dinv[s];
    }
}

// ---------------- GCN aggregation: one warp per node, gather-based --------
// out[n] = dinv[n] * ( dinv[n]*hw[n] + sum_{s in in(n)} dinv[s]*hw[s] )
template <int C>
__global__ void agg_kernel(const float* __restrict__ hw,
                           float* __restrict__ out, int N) {
    int warp = (blockIdx.x * blockDim.x + threadIdx.x) >> 5;
    int lane = threadIdx.x & 31;
    if (warp >= N) return;
    int n = warp;
    float dn = g_dinv[n];
    int start = g_rowptr[n];
    int end = g_rowptr[n + 1];

    if (C == 64) {
        float2 sv = *(const float2*)(hw + (size_t)n * 64 + lane * 2);
        float a0 = dn * sv.x, a1 = dn * sv.y;
        for (int i = start; i < end; i += 32) {
            int m = end - i;
            if (m > 32) m = 32;
            int s = 0;
            float w = 0.f;
            if (lane < m) { s = g_csrc[i + lane]; w = g_csrw[i + lane]; }
#pragma unroll 4
            for (int j = 0; j < m; ++j) {
                int sj = __shfl_sync(0xffffffffu, s, j);
                float wj = __shfl_sync(0xffffffffu, w, j);
                float2 v = *(const float2*)(hw + (size_t)sj * 64 + lane * 2);
                a0 += wj * v.x;
                a1 += wj * v.y;
            }
        }
        float2 o;
        o.x = dn * a0;
        o.y = dn * a1;
        *(float2*)(out + (size_t)n * 64 + lane * 2) = o;
    } else {  // C == 32
        float a0 = dn * hw[(size_t)n * 32 + lane];
        for (int i = start; i < end; i += 32) {
            int m = end - i;
            if (m > 32) m = 32;
            int s = 0;
            float w = 0.f;
            if (lane < m) { s = g_csrc[i + lane]; w = g_csrw[i + lane]; }
#pragma unroll 4
            for (int j = 0; j < m; ++j) {
                int sj = __shfl_sync(0xffffffffu, s, j);
                float wj = __shfl_sync(0xffffffffu, w, j);
                a0 += wj * hw[(size_t)sj * 32 + lane];
            }
        }
        out[(size_t)n * 32 + lane] = dn * a0;
    }
}

// ---------------- driver ---------------------------------------------------
extern "C" void kernel_launch(void* const* d_in, const int* in_sizes, int n_in,
                              void* d_out, int out_size) {
    const float* x   = (const float*)d_in[0];
    const int*   ei  = (const int*)d_in[1];
    const float* W1  = (const float*)d_in[2];
    const float* g1  = (const float*)d_in[4];
    const float* be1 = (const float*)d_in[5];
    const float* W2  = (const float*)d_in[6];
    const float* g2  = (const float*)d_in[8];
    const float* be2 = (const float*)d_in[9];
    const float* Wg1 = (const float*)d_in[10];
    const float* g3  = (const float*)d_in[12];
    const float* be3 = (const float*)d_in[13];
    const float* Wg2 = (const float*)d_in[14];
    const float* g4  = (const float*)d_in[16];
    const float* be4 = (const float*)d_in[17];
    // (all bias vectors are mathematically cancelled by batch-stat BN; skipped)

    const int N = in_sizes[0] / 512;
    const int E = in_sizes[1] / 2;
    const float invM = 1.f / (float)N;

    float *p_h1, *p_h2, *p_hw, *p_agg, *p_hw2, *p_agg2;
    cudaGetSymbolAddress((void**)&p_h1, g_h1);
    cudaGetSymbolAddress((void**)&p_h2, g_h2);
    cudaGetSymbolAddress((void**)&p_hw, g_hw);
    cudaGetSymbolAddress((void**)&p_agg, g_agg);
    cudaGetSymbolAddress((void**)&p_hw2, g_hw2);
    cudaGetSymbolAddress((void**)&p_agg2, g_agg2);

    const int nbN = (N + 255) / 256;
    const int nbE = (E + 255) / 256;
    const int nbScan = (N + 1023) / 1024;

    // Graph structure (built once, reused by both GCN layers)
    zero_indeg_kernel<<<nbN, 256>>>(N);
    count_kernel<<<nbE, 256>>>(ei, E);
    dinv_kernel<<<nbN, 256>>>(N);
    scan1_kernel<<<nbScan, 1024>>>(N);
    scan2_kernel<<<1, 256>>>(nbScan);
    scan3_kernel<<<nbN, 256>>>(N, E);
    fill_kernel<<<nbE, 256>>>(ei, E);

    // encoder_L1: Linear(512,128) + BN(eps 1e-3) + ELU
    gemm_tiled<128><<<(N + 127) / 128, 256>>>(x, W1, p_h1, N, 512);
    zero_stats_kernel<<<1, 128>>>();
    colstats_kernel<128><<<128, 256>>>(p_h1, N);
    bn_finalize_kernel<<<1, 128>>>(g1, be1, 128, invM, 1e-3f);
    bn_apply_kernel<128, 1><<<1024, 256>>>(p_h1, p_h1, N);

    // encoder_L2: Linear(128,64) + BN(eps 1e-3) + ELU
    gemm_tiled<64><<<(N + 127) / 128, 128>>>(p_h1, W2, p_h2, N, 128);
    zero_stats_kernel<<<1, 128>>>();
    colstats_kernel<64><<<128, 256>>>(p_h2, N);
    bn_finalize_kernel<<<1, 128>>>(g2, be2, 64, invM, 1e-3f);
    bn_apply_kernel<64, 1><<<1024, 256>>>(p_h2, p_h2, N);

    // gc1: GCNConv(64,64) + BN(eps 1e-5) + ReLU
    gemm_tiled<64><<<(N + 127) / 128, 128>>>(p_h2, Wg1, p_hw, N, 64);
    agg_kernel<64><<<(N * 32 + 255) / 256, 256>>>(p_hw, p_agg, N);
    zero_stats_kernel<<<1, 128>>>();
    colstats_kernel<64><<<128, 256>>>(p_agg, N);
    bn_finalize_kernel<<<1, 128>>>(g3, be3, 64, invM, 1e-5f);
    bn_apply_kernel<64, 2><<<1024, 256>>>(p_agg, p_agg, N);

    // gc2: GCNConv(64,32) + BN(eps 1e-5), identity activation -> d_out
    gemm_tiled<32><<<(N + 127) / 128, 64>>>(p_agg, Wg2, p_hw2, N, 64);
    agg_kernel<32><<<(N * 32 + 255) / 256, 256>>>(p_hw2, p_agg2, N);
    zero_stats_kernel<<<1, 128>>>();
    colstats_kernel<32><<<128, 256>>>(p_agg2, N);
    bn_finalize_kernel<<<1, 128>>>(g4, be4, 32, invM, 1e-5f);
    bn_apply_kernel<32, 0><<<1024, 256>>>(p_agg2, (float*)d_out, N);
}

// round 5
// speedup vs baseline: 2.0999x; 2.0999x over previous
#include <cuda_runtime.h>
#include <math.h>
#include <cstdint>

#define MAXN 100000
#define MAXE 3200000

// ---------------- device scratch (no allocations allowed) ----------------
__device__ float g_h1[MAXN * 128];
__device__ float g_h2[MAXN * 64];
__device__ float g_hw[MAXN * 64];
__device__ float g_agg[MAXN * 64];
__device__ float g_hw2[MAXN * 32];
__device__ float g_agg2[MAXN * 32];
__device__ float g_wt[128 * 512];          // transposed weight scratch (reused)
__device__ int   g_indeg[MAXN];
__device__ float g_dinv[MAXN];
__device__ int   g_rowptr[MAXN + 1];
__device__ int   g_cursor[MAXN];
__device__ int   g_csrc[MAXE];
__device__ float g_csrw[MAXE];
__device__ float g_sum[128];
__device__ float g_sq[128];
__device__ float g_scale[128];
__device__ float g_shift[128];
__device__ int   g_bsums[256];

// ---------------- tf32 helpers (sm_80+ PTX, valid on sm_103 target) -------
__device__ __forceinline__ uint32_t f2tf32(float x) {
    uint32_t r;
    asm("cvt.rna.tf32.f32 %0, %1;" : "=r"(r) : "f"(x));
    return r;
}

__device__ __forceinline__ void mma_m16n8k8(float* c, const uint32_t* a,
                                            const uint32_t* b) {
    asm volatile(
        "mma.sync.aligned.m16n8k8.row.col.f32.tf32.tf32.f32 "
        "{%0,%1,%2,%3}, {%4,%5,%6,%7}, {%8,%9}, {%0,%1,%2,%3};"
        : "+f"(c[0]), "+f"(c[1]), "+f"(c[2]), "+f"(c[3])
        : "r"(a[0]), "r"(a[1]), "r"(a[2]), "r"(a[3]), "r"(b[0]), "r"(b[1]));
}

// split f32 vec into tf32-exact hi + residual lo
__device__ __forceinline__ void split4(uint4& hi, float4& lo, float4 v) {
    hi.x = f2tf32(v.x); hi.y = f2tf32(v.y);
    hi.z = f2tf32(v.z); hi.w = f2tf32(v.w);
    lo.x = v.x - __uint_as_float(hi.x);
    lo.y = v.y - __uint_as_float(hi.y);
    lo.z = v.z - __uint_as_float(hi.z);
    lo.w = v.w - __uint_as_float(hi.w);
}

// ---------------- tensor-core tf32 GEMM: C[M,BN] = A[M,K] @ Bt[BN,K]^T ----
// 3xTF32 split (Ah*Bh + Al*Bh + Ah*Bl) -> fp32-level accuracy.
// BM=128 per CTA, warp tile 32x32, K chunked by 32, padded smem rows (36).
template <int BN>
__global__ void __launch_bounds__(BN * 4)
mma_gemm(const float* __restrict__ A, const float* __restrict__ Bt,
         float* __restrict__ C, int M, int K) {
    constexpr int LD = 36;           // row pad: bank = lane + const (conflict-free)
    constexpr int T  = BN * 4;       // threads
    constexpr int NWN = BN / 32;     // warps along N
    extern __shared__ float smf[];
    float* AsH = smf;                // 128 x LD
    float* AsL = smf + 128 * LD;
    float* BsH = smf + 2 * 128 * LD; // BN x LD
    float* BsL = BsH + BN * LD;

    const int tid = threadIdx.x;
    const int wid = tid >> 5, lane = tid & 31;
    const int wm = wid / NWN, wn = wid % NWN;   // warp tile origin (wm*32, wn*32)
    const int g = lane >> 2, t = lane & 3;
    const int m0 = blockIdx.x * 128;

    float c[2][4][4];
#pragma unroll
    for (int i = 0; i < 2; i++)
#pragma unroll
        for (int j = 0; j < 4; j++)
#pragma unroll
            for (int k = 0; k < 4; k++) c[i][j][k] = 0.f;

    const int NT = K >> 5;
    for (int kt = 0; kt < NT; ++kt) {
        if (kt > 0) __syncthreads();   // previous chunk fully consumed
        // A chunk: 128 rows x 32 cols = 1024 float4
#pragma unroll
        for (int i = 0; i < 1024 / T; i++) {
            int f = tid + i * T;
            int row = f >> 3, c4 = f & 7;
            float4 v = make_float4(0.f, 0.f, 0.f, 0.f);
            if (m0 + row < M)
                v = *(const float4*)(A + (size_t)(m0 + row) * K + kt * 32 + c4 * 4);
            uint4 hv; float4 lv;
            split4(hv, lv, v);
            *(uint4*)(AsH + row * LD + c4 * 4)  = hv;
            *(float4*)(AsL + row * LD + c4 * 4) = lv;
        }
        // B chunk: BN rows x 32 cols = BN*8 float4 (always 2 per thread)
#pragma unroll
        for (int i = 0; i < 2; i++) {
            int f = tid + i * T;
            int row = f >> 3, c4 = f & 7;
            float4 v = *(const float4*)(Bt + (size_t)row * K + kt * 32 + c4 * 4);
            uint4 hv; float4 lv;
            split4(hv, lv, v);
            *(uint4*)(BsH + row * LD + c4 * 4)  = hv;
            *(float4*)(BsL + row * LD + c4 * 4) = lv;
        }
        __syncthreads();

#pragma unroll
        for (int ks = 0; ks < 4; ++ks) {
            const int k8 = ks * 8;
            uint32_t ah[2][4], al[2][4], bh[4][2], bl[4][2];
#pragma unroll
            for (int ma = 0; ma < 2; ma++) {
                int r = wm * 32 + ma * 16 + g;
                ah[ma][0] = __float_as_uint(AsH[r * LD + k8 + t]);
                ah[ma][1] = __float_as_uint(AsH[(r + 8) * LD + k8 + t]);
                ah[ma][2] = __float_as_uint(AsH[r * LD + k8 + t + 4]);
                ah[ma][3] = __float_as_uint(AsH[(r + 8) * LD + k8 + t + 4]);
                al[ma][0] = __float_as_uint(AsL[r * LD + k8 + t]);
                al[ma][1] = __float_as_uint(AsL[(r + 8) * LD + k8 + t]);
                al[ma][2] = __float_as_uint(AsL[r * LD + k8 + t + 4]);
                al[ma][3] = __float_as_uint(AsL[(r + 8) * LD + k8 + t + 4]);
            }
#pragma unroll
            for (int nb = 0; nb < 4; nb++) {
                int n = wn * 32 + nb * 8 + g;
                bh[nb][0] = __float_as_uint(BsH[n * LD + k8 + t]);
                bh[nb][1] = __float_as_uint(BsH[n * LD + k8 + t + 4]);
                bl[nb][0] = __float_as_uint(BsL[n * LD + k8 + t]);
                bl[nb][1] = __float_as_uint(BsL[n * LD + k8 + t + 4]);
            }
#pragma unroll
            for (int ma = 0; ma < 2; ma++)
#pragma unroll
                for (int nb = 0; nb < 4; nb++) {
                    mma_m16n8k8(c[ma][nb], ah[ma], bh[nb]);
                    mma_m16n8k8(c[ma][nb], al[ma], bh[nb]);
                    mma_m16n8k8(c[ma][nb], ah[ma], bl[nb]);
                }
        }
    }

    // epilogue: c0,c1 at (g, 2t/2t+1), c2,c3 at (g+8, ...)
#pragma unroll
    for (int ma = 0; ma < 2; ma++) {
        int r0 = m0 + wm * 32 + ma * 16 + g;
#pragma unroll
        for (int nb = 0; nb < 4; nb++) {
            int col = wn * 32 + nb * 8 + 2 * t;
            if (r0 < M)
                *(float2*)(C + (size_t)r0 * BN + col) =
                    make_float2(c[ma][nb][0], c[ma][nb][1]);
            if (r0 + 8 < M)
                *(float2*)(C + (size_t)(r0 + 8) * BN + col) =
                    make_float2(c[ma][nb][2], c[ma][nb][3]);
        }
    }
}

static constexpr int smem_mma(int bn) { return (2 * 128 * 36 + 2 * bn * 36) * 4; }

// weight transpose: W[K,N] row-major -> Wt[N,K] row-major
__global__ void transpose_kernel(const float* __restrict__ W,
                                 float* __restrict__ Wt, int K, int N) {
    int i = blockIdx.x * blockDim.x + threadIdx.x;
    if (i < K * N) {
        int k = i / N, n = i % N;
        Wt[n * K + k] = W[i];
    }
}

// ---------------- BatchNorm (training mode, batch stats) ------------------
__global__ void zero_stats_kernel() {
    if (threadIdx.x < 128) { g_sum[threadIdx.x] = 0.f; g_sq[threadIdx.x] = 0.f; }
}

template <int C>
__global__ void colstats_kernel(const float* __restrict__ h, int M) {
    int gtid = blockIdx.x * blockDim.x + threadIdx.x;
    int c = gtid & (C - 1);
    int r0 = gtid / C;
    int stride = (gridDim.x * blockDim.x) / C;
    float s = 0.f, q = 0.f;
    for (int r = r0; r < M; r += stride) {
        float v = h[(size_t)r * C + c];
        s += v;
        q += v * v;
    }
    atomicAdd(&g_sum[c], s);
    atomicAdd(&g_sq[c], q);
}

__global__ void bn_finalize_kernel(const float* __restrict__ gamma,
                                   const float* __restrict__ beta,
                                   int C, float invM, float eps) {
    int c = threadIdx.x;
    if (c < C) {
        float mean = g_sum[c] * invM;
        float var = g_sq[c] * invM - mean * mean;
        float sc = gamma[c] * rsqrtf(var + eps);
        g_scale[c] = sc;
        g_shift[c] = beta[c] - mean * sc;
    }
}

// ACT: 0 = identity, 1 = ELU, 2 = ReLU
template <int C, int ACT>
__global__ void bn_apply_kernel(const float* __restrict__ in,
                                float* __restrict__ out, int M) {
    int total4 = M * C / 4;
    for (int idx = blockIdx.x * blockDim.x + threadIdx.x; idx < total4;
         idx += gridDim.x * blockDim.x) {
        float4 v = ((const float4*)in)[idx];
        int c = (idx * 4) & (C - 1);
        float r[4] = {v.x, v.y, v.z, v.w};
#pragma unroll
        for (int j = 0; j < 4; j++) {
            float t = r[j] * g_scale[c + j] + g_shift[c + j];
            if (ACT == 1) t = (t > 0.f) ? t : expm1f(t);
            else if (ACT == 2) t = (t > 0.f) ? t : 0.f;
            r[j] = t;
        }
        ((float4*)out)[idx] = make_float4(r[0], r[1], r[2], r[3]);
    }
}

// ---------------- graph structure: degrees + CSR build --------------------
__global__ void zero_indeg_kernel(int N) {
    int i = blockIdx.x * blockDim.x + threadIdx.x;
    if (i < N) g_indeg[i] = 0;
}
__global__ void count_kernel(const int* __restrict__ ei, int E) {
    int e = blockIdx.x * blockDim.x + threadIdx.x;
    if (e < E) atomicAdd(&g_indeg[ei[E + e]], 1);
}
__global__ void dinv_kernel(int N) {
    int i = blockIdx.x * blockDim.x + threadIdx.x;
    if (i < N) g_dinv[i] = rsqrtf((float)(g_indeg[i] + 1));  // +1 self loop
}
__global__ void scan1_kernel(int N) {
    __shared__ int sh[1024];
    int tid = threadIdx.x;
    int i = blockIdx.x * 1024 + tid;
    int v = (i < N) ? g_indeg[i] : 0;
    sh[tid] = v;
    __syncthreads();
    for (int off = 1; off < 1024; off <<= 1) {
        int t = (tid >= off) ? sh[tid - off] : 0;
        __syncthreads();
        sh[tid] += t;
        __syncthreads();
    }
    if (i < N) g_rowptr[i] = sh[tid] - v;  // block-local exclusive
    if (tid == 1023) g_bsums[blockIdx.x] = sh[1023];
}
__global__ void scan2_kernel(int nb) {
    __shared__ int sh[256];
    int tid = threadIdx.x;
    int v = (tid < nb) ? g_bsums[tid] : 0;
    sh[tid] = v;
    __syncthreads();
    for (int off = 1; off < 256; off <<= 1) {
        int t = (tid >= off) ? sh[tid - off] : 0;
        __syncthreads();
        sh[tid] += t;
        __syncthreads();
    }
    if (tid < nb) g_bsums[tid] = sh[tid] - v;  // exclusive block offsets
}
__global__ void scan3_kernel(int N, int E) {
    int i = blockIdx.x * blockDim.x + threadIdx.x;
    if (i < N) {
        int v = g_rowptr[i] + g_bsums[i >> 10];
        g_rowptr[i] = v;
        g_cursor[i] = v;
    }
    if (i == 0) g_rowptr[N] = E;
}
__global__ void fill_kernel(const int* __restrict__ ei, int E) {
    int e = blockIdx.x * blockDim.x + threadIdx.x;
    if (e < E) {
        int s = ei[e], d = ei[E + e];
        int p = atomicAdd(&g_cursor[d], 1);
        g_csrc[p] = s;
        g_csrw[p] = g_dinv[s];
    }
}

// ---------------- GCN aggregation: one warp per node, gather-based --------
template <int C>
__global__ void agg_kernel(const float* __restrict__ hw,
                           float* __restrict__ out, int N) {
    int warp = (blockIdx.x * blockDim.x + threadIdx.x) >> 5;
    int lane = threadIdx.x & 31;
    if (warp >= N) return;
    int n = warp;
    float dn = g_dinv[n];
    int start = g_rowptr[n];
    int end = g_rowptr[n + 1];

    if (C == 64) {
        float2 sv = *(const float2*)(hw + (size_t)n * 64 + lane * 2);
        float a0 = dn * sv.x, a1 = dn * sv.y;
        for (int i = start; i < end; i += 32) {
            int m = end - i;
            if (m > 32) m = 32;
            int s = 0;
            float w = 0.f;
            if (lane < m) { s = g_csrc[i + lane]; w = g_csrw[i + lane]; }
#pragma unroll 4
            for (int j = 0; j < m; ++j) {
                int sj = __shfl_sync(0xffffffffu, s, j);
                float wj = __shfl_sync(0xffffffffu, w, j);
                float2 v = *(const float2*)(hw + (size_t)sj * 64 + lane * 2);
                a0 += wj * v.x;
                a1 += wj * v.y;
            }
        }
        float2 o;
        o.x = dn * a0;
        o.y = dn * a1;
        *(float2*)(out + (size_t)n * 64 + lane * 2) = o;
    } else {  // C == 32
        float a0 = dn * hw[(size_t)n * 32 + lane];
        for (int i = start; i < end; i += 32) {
            int m = end - i;
            if (m > 32) m = 32;
            int s = 0;
            float w = 0.f;
            if (lane < m) { s = g_csrc[i + lane]; w = g_csrw[i + lane]; }
#pragma unroll 4
            for (int j = 0; j < m; ++j) {
                int sj = __shfl_sync(0xffffffffu, s, j);
                float wj = __shfl_sync(0xffffffffu, w, j);
                a0 += wj * hw[(size_t)sj * 32 + lane];
            }
        }
        out[(size_t)n * 32 + lane] = dn * a0;
    }
}

// ---------------- driver ---------------------------------------------------
extern "C" void kernel_launch(void* const* d_in, const int* in_sizes, int n_in,
                              void* d_out, int out_size) {
    const float* x   = (const float*)d_in[0];
    const int*   ei  = (const int*)d_in[1];
    const float* W1  = (const float*)d_in[2];
    const float* g1  = (const float*)d_in[4];
    const float* be1 = (const float*)d_in[5];
    const float* W2  = (const float*)d_in[6];
    const float* g2  = (const float*)d_in[8];
    const float* be2 = (const float*)d_in[9];
    const float* Wg1 = (const float*)d_in[10];
    const float* g3  = (const float*)d_in[12];
    const float* be3 = (const float*)d_in[13];
    const float* Wg2 = (const float*)d_in[14];
    const float* g4  = (const float*)d_in[16];
    const float* be4 = (const float*)d_in[17];
    // (all bias vectors are mathematically cancelled by batch-stat BN; skipped)

    const int N = in_sizes[0] / 512;
    const int E = in_sizes[1] / 2;
    const float invM = 1.f / (float)N;

    float *p_h1, *p_h2, *p_hw, *p_agg, *p_hw2, *p_agg2, *p_wt;
    cudaGetSymbolAddress((void**)&p_h1, g_h1);
    cudaGetSymbolAddress((void**)&p_h2, g_h2);
    cudaGetSymbolAddress((void**)&p_hw, g_hw);
    cudaGetSymbolAddress((void**)&p_agg, g_agg);
    cudaGetSymbolAddress((void**)&p_hw2, g_hw2);
    cudaGetSymbolAddress((void**)&p_agg2, g_agg2);
    cudaGetSymbolAddress((void**)&p_wt, g_wt);

    cudaFuncSetAttribute(mma_gemm<128>, cudaFuncAttributeMaxDynamicSharedMemorySize, smem_mma(128));
    cudaFuncSetAttribute(mma_gemm<64>,  cudaFuncAttributeMaxDynamicSharedMemorySize, smem_mma(64));
    cudaFuncSetAttribute(mma_gemm<32>,  cudaFuncAttributeMaxDynamicSharedMemorySize, smem_mma(32));

    const int nbN = (N + 255) / 256;
    const int nbE = (E + 255) / 256;
    const int nbScan = (N + 1023) / 1024;
    const int nbM = (N + 127) / 128;

    // Graph structure (built once, reused by both GCN layers)
    zero_indeg_kernel<<<nbN, 256>>>(N);
    count_kernel<<<nbE, 256>>>(ei, E);
    dinv_kernel<<<nbN, 256>>>(N);
    scan1_kernel<<<nbScan, 1024>>>(N);
    scan2_kernel<<<1, 256>>>(nbScan);
    scan3_kernel<<<nbN, 256>>>(N, E);
    fill_kernel<<<nbE, 256>>>(ei, E);

    // encoder_L1: Linear(512,128) + BN(eps 1e-3) + ELU
    transpose_kernel<<<(512 * 128 + 255) / 256, 256>>>(W1, p_wt, 512, 128);
    mma_gemm<128><<<nbM, 512, smem_mma(128)>>>(x, p_wt, p_h1, N, 512);
    zero_stats_kernel<<<1, 128>>>();
    colstats_kernel<128><<<128, 256>>>(p_h1, N);
    bn_finalize_kernel<<<1, 128>>>(g1, be1, 128, invM, 1e-3f);
    bn_apply_kernel<128, 1><<<1024, 256>>>(p_h1, p_h1, N);

    // encoder_L2: Linear(128,64) + BN(eps 1e-3) + ELU
    transpose_kernel<<<(128 * 64 + 255) / 256, 256>>>(W2, p_wt, 128, 64);
    mma_gemm<64><<<nbM, 256, smem_mma(64)>>>(p_h1, p_wt, p_h2, N, 128);
    zero_stats_kernel<<<1, 128>>>();
    colstats_kernel<64><<<128, 256>>>(p_h2, N);
    bn_finalize_kernel<<<1, 128>>>(g2, be2, 64, invM, 1e-3f);
    bn_apply_kernel<64, 1><<<1024, 256>>>(p_h2, p_h2, N);

    // gc1: GCNConv(64,64) + BN(eps 1e-5) + ReLU
    transpose_kernel<<<(64 * 64 + 255) / 256, 256>>>(Wg1, p_wt, 64, 64);
    mma_gemm<64><<<nbM, 256, smem_mma(64)>>>(p_h2, p_wt, p_hw, N, 64);
    agg_kernel<64><<<(N * 32 + 255) / 256, 256>>>(p_hw, p_agg, N);
    zero_stats_kernel<<<1, 128>>>();
    colstats_kernel<64><<<128, 256>>>(p_agg, N);
    bn_finalize_kernel<<<1, 128>>>(g3, be3, 64, invM, 1e-5f);
    bn_apply_kernel<64, 2><<<1024, 256>>>(p_agg, p_agg, N);

    // gc2: GCNConv(64,32) + BN(eps 1e-5), identity activation -> d_out
    transpose_kernel<<<(64 * 32 + 255) / 256, 256>>>(Wg2, p_wt, 64, 32);
    mma_gemm<32><<<nbM, 128, smem_mma(32)>>>(p_agg, p_wt, p_hw2, N, 64);
    agg_kernel<32><<<(N * 32 + 255) / 256, 256>>>(p_hw2, p_agg2, N);
    zero_stats_kernel<<<1, 128>>>();
    colstats_kernel<32><<<128, 256>>>(p_agg2, N);
    bn_finalize_kernel<<<1, 128>>>(g4, be4, 32, invM, 1e-5f);
    bn_apply_kernel<32, 0><<<1024, 256>>>(p_agg2, (float*)d_out, N);
}

// round 7
// speedup vs baseline: 2.2453x; 1.0693x over previous
#include <cuda_runtime.h>
#include <math.h>
#include <cstdint>

#define MAXN 100000
#define MAXE 3200000

// ---------------- device scratch (no allocations allowed) ----------------
__device__ float g_h1[MAXN * 128];
__device__ float g_h2[MAXN * 64];
__device__ float g_hw[MAXN * 64];
__device__ float g_agg[MAXN * 64];
__device__ float g_hw2[MAXN * 32];
__device__ float g_agg2[MAXN * 32];
__device__ float g_wt1[512 * 128];
__device__ float g_wt2[128 * 64];
__device__ float g_wt3[64 * 64];
__device__ float g_wt4[64 * 32];
__device__ float g_stats[4][2][128];       // per-layer raw col sum / sumsq
__device__ int   g_indeg[MAXN];
__device__ float g_dinv[MAXN];
__device__ int   g_rowptr[MAXN + 1];
__device__ int   g_cursor[MAXN];
__device__ int   g_csrc[MAXE];
__device__ float g_csrw[MAXE];
__device__ int   g_bsums[256];

// ---------------- tf32 helpers (sm_80+ PTX, valid on sm_103 target) -------
__device__ __forceinline__ uint32_t f2tf32(float x) {
    uint32_t r;
    asm("cvt.rna.tf32.f32 %0, %1;" : "=r"(r) : "f"(x));
    return r;
}

__device__ __forceinline__ void mma_m16n8k8(float* c, const uint32_t* a,
                                            const uint32_t* b) {
    asm volatile(
        "mma.sync.aligned.m16n8k8.row.col.f32.tf32.tf32.f32 "
        "{%0,%1,%2,%3}, {%4,%5,%6,%7}, {%8,%9}, {%0,%1,%2,%3};"
        : "+f"(c[0]), "+f"(c[1]), "+f"(c[2]), "+f"(c[3])
        : "r"(a[0]), "r"(a[1]), "r"(a[2]), "r"(a[3]), "r"(b[0]), "r"(b[1]));
}

// split f32 vec into tf32-exact hi + residual lo
__device__ __forceinline__ void split4(uint4& hi, float4& lo, float4 v) {
    hi.x = f2tf32(v.x); hi.y = f2tf32(v.y);
    hi.z = f2tf32(v.z); hi.w = f2tf32(v.w);
    lo.x = v.x - __uint_as_float(hi.x);
    lo.y = v.y - __uint_as_float(hi.y);
    lo.z = v.z - __uint_as_float(hi.z);
    lo.w = v.w - __uint_as_float(hi.w);
}

__device__ __forceinline__ float act_f(float t, int ACT) {
    if (ACT == 1) return (t > 0.f) ? t : expm1f(t);
    if (ACT == 2) return (t > 0.f) ? t : 0.f;
    return t;
}

// ---------------- tensor-core tf32 GEMM: C[M,BN] = A'[M,K] @ Bt[BN,K]^T ---
// A' = act(A*scale + shift) when FUSE (BN of the producing layer folded into
// the A-tile load). 3xTF32 split -> fp32-level accuracy.
// BM=128 per CTA, warp tile 32x32, K chunked by 32, padded smem rows (36).
// Register-staged double buffering: next chunk's LDGs issued before MMA.
template <int BN, int ACT, bool FUSE>
__global__ void __launch_bounds__(BN * 4)
mma_gemm(const float* __restrict__ A, const float* __restrict__ Bt,
         float* __restrict__ C, int M, int K,
         const float* __restrict__ sumv, const float* __restrict__ sqv,
         const float* __restrict__ gamma, const float* __restrict__ beta,
         float eps, float invM) {
    constexpr int LD = 36;           // row pad: conflict-free frag LDS
    constexpr int T  = BN * 4;       // threads
    constexpr int NWN = BN / 32;     // warps along N
    constexpr int APT = 1024 / T;    // A float4s per thread per chunk
    extern __shared__ float smf[];
    float* AsH = smf;                // 128 x LD
    float* AsL = smf + 128 * LD;
    float* BsH = smf + 2 * 128 * LD; // BN x LD
    float* BsL = BsH + BN * LD;
    float* scaleS = BsL + BN * LD;   // [128] (only when FUSE)
    float* shiftS = scaleS + 128;

    const int tid = threadIdx.x;
    const int wid = tid >> 5, lane = tid & 31;
    const int wm = wid / NWN, wn = wid % NWN;
    const int g = lane >> 2, t = lane & 3;
    const int m0 = blockIdx.x * 128;

    if (FUSE) {
        for (int c = tid; c < K; c += T) {
            float mean = sumv[c] * invM;
            float var = sqv[c] * invM - mean * mean;
            float sc = gamma[c] * rsqrtf(var + eps);
            scaleS[c] = sc;
            shiftS[c] = beta[c] - mean * sc;
        }
    }

    float c[2][4][4];
#pragma unroll
    for (int i = 0; i < 2; i++)
#pragma unroll
        for (int j = 0; j < 4; j++)
#pragma unroll
            for (int k = 0; k < 4; k++) c[i][j][k] = 0.f;

    float4 aReg[APT], bReg[2];

    auto ldg_tile = [&](int kt) {
#pragma unroll
        for (int i = 0; i < APT; i++) {
            int f = tid + i * T;
            int row = f >> 3, c4 = f & 7;
            aReg[i] = make_float4(0.f, 0.f, 0.f, 0.f);
            if (m0 + row < M)
                aReg[i] = *(const float4*)(A + (size_t)(m0 + row) * K + kt * 32 + c4 * 4);
        }
#pragma unroll
        for (int i = 0; i < 2; i++) {
            int f = tid + i * T;
            int row = f >> 3, c4 = f & 7;
            bReg[i] = *(const float4*)(Bt + (size_t)row * K + kt * 32 + c4 * 4);
        }
    };
    auto sts_tile = [&](int kt) {
#pragma unroll
        for (int i = 0; i < APT; i++) {
            int f = tid + i * T;
            int row = f >> 3, c4 = f & 7;
            float4 v = aReg[i];
            if (FUSE) {
                int cb = kt * 32 + c4 * 4;
                v.x = act_f(v.x * scaleS[cb + 0] + shiftS[cb + 0], ACT);
                v.y = act_f(v.y * scaleS[cb + 1] + shiftS[cb + 1], ACT);
                v.z = act_f(v.z * scaleS[cb + 2] + shiftS[cb + 2], ACT);
                v.w = act_f(v.w * scaleS[cb + 3] + shiftS[cb + 3], ACT);
            }
            uint4 hv; float4 lv;
            split4(hv, lv, v);
            *(uint4*)(AsH + row * LD + c4 * 4)  = hv;
            *(float4*)(AsL + row * LD + c4 * 4) = lv;
        }
#pragma unroll
        for (int i = 0; i < 2; i++) {
            int f = tid + i * T;
            int row = f >> 3, c4 = f & 7;
            uint4 hv; float4 lv;
            split4(hv, lv, bReg[i]);
            *(uint4*)(BsH + row * LD + c4 * 4)  = hv;
            *(float4*)(BsL + row * LD + c4 * 4) = lv;
        }
    };
    auto mma_chunk = [&]() {
#pragma unroll
        for (int ks = 0; ks < 4; ++ks) {
            const int k8 = ks * 8;
            uint32_t ah[2][4], al[2][4], bh[4][2], bl[4][2];
#pragma unroll
            for (int ma = 0; ma < 2; ma++) {
                int r = wm * 32 + ma * 16 + g;
                ah[ma][0] = __float_as_uint(AsH[r * LD + k8 + t]);
                ah[ma][1] = __float_as_uint(AsH[(r + 8) * LD + k8 + t]);
                ah[ma][2] = __float_as_uint(AsH[r * LD + k8 + t + 4]);
                ah[ma][3] = __float_as_uint(AsH[(r + 8) * LD + k8 + t + 4]);
                al[ma][0] = __float_as_uint(AsL[r * LD + k8 + t]);
                al[ma][1] = __float_as_uint(AsL[(r + 8) * LD + k8 + t]);
                al[ma][2] = __float_as_uint(AsL[r * LD + k8 + t + 4]);
                al[ma][3] = __float_as_uint(AsL[(r + 8) * LD + k8 + t + 4]);
            }
#pragma unroll
            for (int nb = 0; nb < 4; nb++) {
                int n = wn * 32 + nb * 8 + g;
                bh[nb][0] = __float_as_uint(BsH[n * LD + k8 + t]);
                bh[nb][1] = __float_as_uint(BsH[n * LD + k8 + t + 4]);
                bl[nb][0] = __float_as_uint(BsL[n * LD + k8 + t]);
                bl[nb][1] = __float_as_uint(BsL[n * LD + k8 + t + 4]);
            }
#pragma unroll
            for (int ma = 0; ma < 2; ma++)
#pragma unroll
                for (int nb = 0; nb < 4; nb++) {
                    mma_m16n8k8(c[ma][nb], ah[ma], bh[nb]);
                    mma_m16n8k8(c[ma][nb], al[ma], bh[nb]);
                    mma_m16n8k8(c[ma][nb], ah[ma], bl[nb]);
                }
        }
    };

    const int NT = K >> 5;
    ldg_tile(0);
    __syncthreads();          // scaleS/shiftS visible (and smem reuse-safe)
    sts_tile(0);
    __syncthreads();
    for (int kt = 0; kt < NT; ++kt) {
        if (kt + 1 < NT) ldg_tile(kt + 1);   // LDGs in flight over MMA
        mma_chunk();
        __syncthreads();
        if (kt + 1 < NT) {
            sts_tile(kt + 1);
            __syncthreads();
        }
    }

#pragma unroll
    for (int ma = 0; ma < 2; ma++) {
        int r0 = m0 + wm * 32 + ma * 16 + g;
#pragma unroll
        for (int nb = 0; nb < 4; nb++) {
            int col = wn * 32 + nb * 8 + 2 * t;
            if (r0 < M)
                *(float2*)(C + (size_t)r0 * BN + col) =
                    make_float2(c[ma][nb][0], c[ma][nb][1]);
            if (r0 + 8 < M)
                *(float2*)(C + (size_t)(r0 + 8) * BN + col) =
                    make_float2(c[ma][nb][2], c[ma][nb][3]);
        }
    }
}

static constexpr int smem_mma(int bn, bool fuse) {
    return (2 * 128 * 36 + 2 * bn * 36) * 4 + (fuse ? 1024 : 0);
}

// ---------------- prep: zero stats + all 4 weight transposes --------------
__global__ void prep_kernel(const float* __restrict__ W1, const float* __restrict__ W2,
                            const float* __restrict__ Wg1, const float* __restrict__ Wg2) {
    int i = blockIdx.x * blockDim.x + threadIdx.x;
    if (i < 1024) ((float*)g_stats)[i] = 0.f;
    if (i < 512 * 128) { int k = i / 128, n = i % 128; g_wt1[n * 512 + k] = W1[i]; }
    if (i < 128 * 64)  { int k = i / 64,  n = i % 64;  g_wt2[n * 128 + k] = W2[i]; }
    if (i < 64 * 64)   { int k = i / 64,  n = i % 64;  g_wt3[n * 64 + k]  = Wg1[i]; }
    if (i < 64 * 32)   { int k = i / 32,  n = i % 32;  g_wt4[n * 64 + k]  = Wg2[i]; }
}

// ---------------- column stats (raw sums; finalize math inlined elsewhere) -
template <int C>
__global__ void colstats_kernel(const float* __restrict__ h, int M,
                                float* __restrict__ sumv, float* __restrict__ sqv) {
    int gtid = blockIdx.x * blockDim.x + threadIdx.x;
    int c = gtid & (C - 1);
    int r0 = gtid / C;
    int stride = (gridDim.x * blockDim.x) / C;
    float s = 0.f, q = 0.f;
    for (int r = r0; r < M; r += stride) {
        float v = h[(size_t)r * C + c];
        s += v;
        q += v * v;
    }
    atomicAdd(&sumv[c], s);
    atomicAdd(&sqv[c], q);
}

// ---------------- final BN apply (inline finalize) -> d_out ---------------
template <int C>
__global__ void bn_out_kernel(const float* __restrict__ in, float* __restrict__ out,
                              int M, const float* __restrict__ sumv,
                              const float* __restrict__ sqv,
                              const float* __restrict__ gamma,
                              const float* __restrict__ beta, float eps, float invM) {
    __shared__ float sc[C], sh[C];
    if (threadIdx.x < C) {
        float mean = sumv[threadIdx.x] * invM;
        float var = sqv[threadIdx.x] * invM - mean * mean;
        float s = gamma[threadIdx.x] * rsqrtf(var + eps);
        sc[threadIdx.x] = s;
        sh[threadIdx.x] = beta[threadIdx.x] - mean * s;
    }
    __syncthreads();
    int total4 = M * C / 4;
    for (int idx = blockIdx.x * blockDim.x + threadIdx.x; idx < total4;
         idx += gridDim.x * blockDim.x) {
        float4 v = ((const float4*)in)[idx];
        int c = (idx * 4) & (C - 1);
        ((float4*)out)[idx] = make_float4(v.x * sc[c + 0] + sh[c + 0],
                                          v.y * sc[c + 1] + sh[c + 1],
                                          v.z * sc[c + 2] + sh[c + 2],
                                          v.w * sc[c + 3] + sh[c + 3]);
    }
}

// ---------------- graph structure: degrees + CSR build --------------------
__global__ void zero_indeg_kernel(int N) {
    int i = blockIdx.x * blockDim.x + threadIdx.x;
    if (i < N) g_indeg[i] = 0;
}
__global__ void count_kernel(const int* __restrict__ ei, int E) {
    int e = blockIdx.x * blockDim.x + threadIdx.x;
    if (e < E) atomicAdd(&g_indeg[ei[E + e]], 1);
}
__global__ void dinv_kernel(int N) {
    int i = blockIdx.x * blockDim.x + threadIdx.x;
    if (i < N) g_dinv[i] = rsqrtf((float)(g_indeg[i] + 1));  // +1 self loop
}
__global__ void scan1_kernel(int N) {
    __shared__ int sh[1024];
    int tid = threadIdx.x;
    int i = blockIdx.x * 1024 + tid;
    int v = (i < N) ? g_indeg[i] : 0;
    sh[tid] = v;
    __syncthreads();
    for (int off = 1; off < 1024; off <<= 1) {
        int t = (tid >= off) ? sh[tid - off] : 0;
        __syncthreads();
        sh[tid] += t;
        __syncthreads();
    }
    if (i < N) g_rowptr[i] = sh[tid] - v;  // block-local exclusive
    if (tid == 1023) g_bsums[blockIdx.x] = sh[1023];
}
__global__ void scan2_kernel(int nb) {
    __shared__ int sh[256];
    int tid = threadIdx.x;
    int v = (tid < nb) ? g_bsums[tid] : 0;
    sh[tid] = v;
    __syncthreads();
    for (int off = 1; off < 256; off <<= 1) {
        int t = (tid >= off) ? sh[tid - off] : 0;
        __syncthreads();
        sh[tid] += t;
        __syncthreads();
    }
    if (tid < nb) g_bsums[tid] = sh[tid] - v;  // exclusive block offsets
}
__global__ void scan3_kernel(int N, int E) {
    int i = blockIdx.x * blockDim.x + threadIdx.x;
    if (i < N) {
        int v = g_rowptr[i] + g_bsums[i >> 10];
        g_rowptr[i] = v;
        g_cursor[i] = v;
    }
    if (i == 0) g_rowptr[N] = E;
}
__global__ void fill_kernel(const int* __restrict__ ei, int E) {
    int e = blockIdx.x * blockDim.x + threadIdx.x;
    if (e < E) {
        int s = ei[e], d = ei[E + e];
        int p = atomicAdd(&g_cursor[d], 1);
        g_csrc[p] = s;
        g_csrw[p] = g_dinv[s];
    }
}

// ---------------- GCN aggregation: one warp per node, gather-based --------
template <int C>
__global__ void agg_kernel(const float* __restrict__ hw,
                           float* __restrict__ out, int N) {
    int warp = (blockIdx.x * blockDim.x + threadIdx.x) >> 5;
    int lane = threadIdx.x & 31;
    if (warp >= N) return;
    int n = warp;
    float dn = g_dinv[n];
    int start = g_rowptr[n];
    int end = g_rowptr[n + 1];

    if (C == 64) {
        float2 sv = *(const float2*)(hw + (size_t)n * 64 + lane * 2);
        float a0 = dn * sv.x, a1 = dn * sv.y;
        for (int i = start; i < end; i += 32) {
            int m = end - i;
            if (m > 32) m = 32;
            int s = 0;
            float w = 0.f;
            if (lane < m) { s = g_csrc[i + lane]; w = g_csrw[i + lane]; }
#pragma unroll 4
            for (int j = 0; j < m; ++j) {
                int sj = __shfl_sync(0xffffffffu, s, j);
                float wj = __shfl_sync(0xffffffffu, w, j);
                float2 v = *(const float2*)(hw + (size_t)sj * 64 + lane * 2);
                a0 += wj * v.x;
                a1 += wj * v.y;
            }
        }
        float2 o;
        o.x = dn * a0;
        o.y = dn * a1;
        *(float2*)(out + (size_t)n * 64 + lane * 2) = o;
    } else {  // C == 32
        float a0 = dn * hw[(size_t)n * 32 + lane];
        for (int i = start; i < end; i += 32) {
            int m = end - i;
            if (m > 32) m = 32;
            int s = 0;
            float w = 0.f;
            if (lane < m) { s = g_csrc[i + lane]; w = g_csrw[i + lane]; }
#pragma unroll 4
            for (int j = 0; j < m; ++j) {
                int sj = __shfl_sync(0xffffffffu, s, j);
                float wj = __shfl_sync(0xffffffffu, w, j);
                a0 += wj * hw[(size_t)sj * 32 + lane];
            }
        }
        out[(size_t)n * 32 + lane] = dn * a0;
    }
}

// ---------------- driver ---------------------------------------------------
extern "C" void kernel_launch(void* const* d_in, const int* in_sizes, int n_in,
                              void* d_out, int out_size) {
    const float* x   = (const float*)d_in[0];
    const int*   ei  = (const int*)d_in[1];
    const float* W1  = (const float*)d_in[2];
    const float* g1  = (const float*)d_in[4];
    const float* be1 = (const float*)d_in[5];
    const float* W2  = (const float*)d_in[6];
    const float* g2  = (const float*)d_in[8];
    const float* be2 = (const float*)d_in[9];
    const float* Wg1 = (const float*)d_in[10];
    const float* g3  = (const float*)d_in[12];
    const float* be3 = (const float*)d_in[13];
    const float* Wg2 = (const float*)d_in[14];
    const float* g4  = (const float*)d_in[16];
    const float* be4 = (const float*)d_in[17];
    // (all bias vectors are mathematically cancelled by batch-stat BN; skipped)

    const int N = in_sizes[0] / 512;
    const int E = in_sizes[1] / 2;
    const float invM = 1.f / (float)N;

    float *p_h1, *p_h2, *p_hw, *p_agg, *p_hw2, *p_agg2;
    float *p_wt1, *p_wt2, *p_wt3, *p_wt4, *p_st;
    cudaGetSymbolAddress((void**)&p_h1, g_h1);
    cudaGetSymbolAddress((void**)&p_h2, g_h2);
    cudaGetSymbolAddress((void**)&p_hw, g_hw);
    cudaGetSymbolAddress((void**)&p_agg, g_agg);
    cudaGetSymbolAddress((void**)&p_hw2, g_hw2);
    cudaGetSymbolAddress((void**)&p_agg2, g_agg2);
    cudaGetSymbolAddress((void**)&p_wt1, g_wt1);
    cudaGetSymbolAddress((void**)&p_wt2, g_wt2);
    cudaGetSymbolAddress((void**)&p_wt3, g_wt3);
    cudaGetSymbolAddress((void**)&p_wt4, g_wt4);
    cudaGetSymbolAddress((void**)&p_st, g_stats);
    // stats layout: layer L sum = p_st + L*256, sq = p_st + L*256 + 128
    float* s0 = p_st;        float* q0 = p_st + 128;
    float* s1 = p_st + 256;  float* q1 = p_st + 384;
    float* s2 = p_st + 512;  float* q2 = p_st + 640;
    float* s3 = p_st + 768;  float* q3 = p_st + 896;

    cudaFuncSetAttribute(mma_gemm<128, 0, false>, cudaFuncAttributeMaxDynamicSharedMemorySize, smem_mma(128, false));
    cudaFuncSetAttribute(mma_gemm<64, 1, true>,   cudaFuncAttributeMaxDynamicSharedMemorySize, smem_mma(64, true));
    cudaFuncSetAttribute(mma_gemm<32, 2, true>,   cudaFuncAttributeMaxDynamicSharedMemorySize, smem_mma(32, true));

    const int nbN = (N + 255) / 256;
    const int nbE = (E + 255) / 256;
    const int nbScan = (N + 1023) / 1024;
    const int nbM = (N + 127) / 128;

    // prep: zero stats + all weight transposes (one kernel)
    prep_kernel<<<(512 * 128 + 255) / 256, 256>>>(W1, W2, Wg1, Wg2);

    // Graph structure (built once, reused by both GCN layers)
    zero_indeg_kernel<<<nbN, 256>>>(N);
    count_kernel<<<nbE, 256>>>(ei, E);
    dinv_kernel<<<nbN, 256>>>(N);
    scan1_kernel<<<nbScan, 1024>>>(N);
    scan2_kernel<<<1, 256>>>(nbScan);
    scan3_kernel<<<nbN, 256>>>(N, E);
    fill_kernel<<<nbE, 256>>>(ei, E);

    // encoder_L1: Linear(512,128); BN+ELU deferred into gemm2's A-load
    mma_gemm<128, 0, false><<<nbM, 512, smem_mma(128, false)>>>(
        x, p_wt1, p_h1, N, 512, nullptr, nullptr, nullptr, nullptr, 0.f, 0.f);
    colstats_kernel<128><<<128, 256>>>(p_h1, N, s0, q0);

    // encoder_L2: A = ELU(BN(h1)); BN+ELU of h2 deferred into gemm3
    mma_gemm<64, 1, true><<<nbM, 256, smem_mma(64, true)>>>(
        p_h1, p_wt2, p_h2, N, 128, s0, q0, g1, be1, 1e-3f, invM);
    colstats_kernel<64><<<128, 256>>>(p_h2, N, s1, q1);

    // gc1: GCNConv = (ELU(BN(h2)) @ Wg1) then aggregate
    mma_gemm<64, 1, true><<<nbM, 256, smem_mma(64, true)>>>(
        p_h2, p_wt3, p_hw, N, 64, s1, q1, g2, be2, 1e-3f, invM);
    agg_kernel<64><<<(N * 32 + 255) / 256, 256>>>(p_hw, p_agg, N);
    colstats_kernel<64><<<128, 256>>>(p_agg, N, s2, q2);

    // gc2: A = ReLU(BN(agg)); aggregate; final BN -> d_out
    mma_gemm<32, 2, true><<<nbM, 128, smem_mma(32, true)>>>(
        p_agg, p_wt4, p_hw2, N, 64, s2, q2, g3, be3, 1e-5f, invM);
    agg_kernel<32><<<(N * 32 + 255) / 256, 256>>>(p_hw2, p_agg2, N);
    colstats_kernel<32><<<128, 256>>>(p_agg2, N, s3, q3);
    bn_out_kernel<32><<<512, 256>>>(p_agg2, (float*)d_out, N, s3, q3, g4, be4,
                                    1e-5f, invM);
}

// round 14
// speedup vs baseline: 2.4216x; 1.0785x over previous
#include <cuda_runtime.h>
#include <math.h>
#include <cstdint>

#define MAXN 100000
#define MAXE 3200000

// ---------------- device scratch (no allocations allowed) ----------------
__device__ float g_h1[MAXN * 128];
__device__ float g_h2[MAXN * 64];
__device__ float g_hw[MAXN * 64];
__device__ float g_agg[MAXN * 64];
__device__ float g_hw2[MAXN * 32];
__device__ float g_agg2[MAXN * 32];
__device__ float g_wt1[512 * 128];
__device__ float g_wt2[128 * 64];
__device__ float g_wt3[64 * 64];
__device__ float g_wt4[64 * 32];
__device__ float g_stats[4][2][128];       // per-layer raw col sum / sumsq
__device__ int   g_indeg[MAXN];
__device__ float g_dinv[MAXN];
__device__ int   g_rowptr[MAXN + 1];
__device__ int   g_cursor[MAXN];
__device__ int   g_csrc[MAXE];
__device__ int   g_bsums[256];

// ---------------- tf32 helpers (sm_80+ PTX, valid on sm_103 target) -------
__device__ __forceinline__ uint32_t f2tf32(float x) {
    uint32_t r;
    asm("cvt.rna.tf32.f32 %0, %1;" : "=r"(r) : "f"(x));
    return r;
}

__device__ __forceinline__ void mma_m16n8k8(float* c, const uint32_t* a,
                                            const uint32_t* b) {
    asm volatile(
        "mma.sync.aligned.m16n8k8.row.col.f32.tf32.tf32.f32 "
        "{%0,%1,%2,%3}, {%4,%5,%6,%7}, {%8,%9}, {%0,%1,%2,%3};"
        : "+f"(c[0]), "+f"(c[1]), "+f"(c[2]), "+f"(c[3])
        : "r"(a[0]), "r"(a[1]), "r"(a[2]), "r"(a[3]), "r"(b[0]), "r"(b[1]));
}

// split f32 vec into tf32-exact hi + residual lo
__device__ __forceinline__ void split4(uint4& hi, float4& lo, float4 v) {
    hi.x = f2tf32(v.x); hi.y = f2tf32(v.y);
    hi.z = f2tf32(v.z); hi.w = f2tf32(v.w);
    lo.x = v.x - __uint_as_float(hi.x);
    lo.y = v.y - __uint_as_float(hi.y);
    lo.z = v.z - __uint_as_float(hi.z);
    lo.w = v.w - __uint_as_float(hi.w);
}

__device__ __forceinline__ float act_f(float t, int ACT) {
    if (ACT == 1) return (t > 0.f) ? t : expm1f(t);
    if (ACT == 2) return (t > 0.f) ? t : 0.f;
    return t;
}

// ---------------- tensor-core tf32 GEMM: C[M,BN] = A'[M,K] @ Bt[BN,K]^T ---
// A' = act(A*scale + shift) when FUSE (producer BN folded into A-tile load).
// SCALE: multiply output row r by g_dinv[r] (GCN normalization pre-fold).
// STATS: accumulate column sum/sumsq of C into sumo/sqo via warp-reduced atomics.
// 3xTF32 split -> fp32-level accuracy. BM=128 per CTA, warp tile 32x32,
// K chunked by 32, padded smem rows (36), register-staged double buffering.
template <int BN, int ACT, bool FUSE, bool SCALE, bool STATS>
__global__ void __launch_bounds__(BN * 4)
mma_gemm(const float* __restrict__ A, const float* __restrict__ Bt,
         float* __restrict__ C, int M, int K,
         const float* __restrict__ sumv, const float* __restrict__ sqv,
         const float* __restrict__ gamma, const float* __restrict__ beta,
         float eps, float invM,
         float* __restrict__ sumo, float* __restrict__ sqo) {
    constexpr int LD = 36;           // row pad: conflict-free frag LDS
    constexpr int T  = BN * 4;       // threads
    constexpr int NWN = BN / 32;     // warps along N
    constexpr int APT = 1024 / T;    // A float4s per thread per chunk
    extern __shared__ float smf[];
    float* AsH = smf;                // 128 x LD
    float* AsL = smf + 128 * LD;
    float* BsH = smf + 2 * 128 * LD; // BN x LD
    float* BsL = BsH + BN * LD;
    float* scaleS = BsL + BN * LD;   // [128] (only when FUSE)
    float* shiftS = scaleS + 128;

    const int tid = threadIdx.x;
    const int wid = tid >> 5, lane = tid & 31;
    const int wm = wid / NWN, wn = wid % NWN;
    const int g = lane >> 2, t = lane & 3;
    const int m0 = blockIdx.x * 128;

    if (FUSE) {
        for (int c = tid; c < K; c += T) {
            float mean = sumv[c] * invM;
            float var = sqv[c] * invM - mean * mean;
            float sc = gamma[c] * rsqrtf(var + eps);
            scaleS[c] = sc;
            shiftS[c] = beta[c] - mean * sc;
        }
    }

    float c[2][4][4];
#pragma unroll
    for (int i = 0; i < 2; i++)
#pragma unroll
        for (int j = 0; j < 4; j++)
#pragma unroll
            for (int k = 0; k < 4; k++) c[i][j][k] = 0.f;

    float4 aReg[APT], bReg[2];

    auto ldg_tile = [&](int kt) {
#pragma unroll
        for (int i = 0; i < APT; i++) {
            int f = tid + i * T;
            int row = f >> 3, c4 = f & 7;
            aReg[i] = make_float4(0.f, 0.f, 0.f, 0.f);
            if (m0 + row < M)
                aReg[i] = *(const float4*)(A + (size_t)(m0 + row) * K + kt * 32 + c4 * 4);
        }
#pragma unroll
        for (int i = 0; i < 2; i++) {
            int f = tid + i * T;
            int row = f >> 3, c4 = f & 7;
            bReg[i] = *(const float4*)(Bt + (size_t)row * K + kt * 32 + c4 * 4);
        }
    };
    auto sts_tile = [&](int kt) {
#pragma unroll
        for (int i = 0; i < APT; i++) {
            int f = tid + i * T;
            int row = f >> 3, c4 = f & 7;
            float4 v = aReg[i];
            if (FUSE) {
                int cb = kt * 32 + c4 * 4;
                v.x = act_f(v.x * scaleS[cb + 0] + shiftS[cb + 0], ACT);
                v.y = act_f(v.y * scaleS[cb + 1] + shiftS[cb + 1], ACT);
                v.z = act_f(v.z * scaleS[cb + 2] + shiftS[cb + 2], ACT);
                v.w = act_f(v.w * scaleS[cb + 3] + shiftS[cb + 3], ACT);
            }
            uint4 hv; float4 lv;
            split4(hv, lv, v);
            *(uint4*)(AsH + row * LD + c4 * 4)  = hv;
            *(float4*)(AsL + row * LD + c4 * 4) = lv;
        }
#pragma unroll
        for (int i = 0; i < 2; i++) {
            int f = tid + i * T;
            int row = f >> 3, c4 = f & 7;
            uint4 hv; float4 lv;
            split4(hv, lv, bReg[i]);
            *(uint4*)(BsH + row * LD + c4 * 4)  = hv;
            *(float4*)(BsL + row * LD + c4 * 4) = lv;
        }
    };
    auto mma_chunk = [&]() {
#pragma unroll
        for (int ks = 0; ks < 4; ++ks) {
            const int k8 = ks * 8;
            uint32_t ah[2][4], al[2][4], bh[4][2], bl[4][2];
#pragma unroll
            for (int ma = 0; ma < 2; ma++) {
                int r = wm * 32 + ma * 16 + g;
                ah[ma][0] = __float_as_uint(AsH[r * LD + k8 + t]);
                ah[ma][1] = __float_as_uint(AsH[(r + 8) * LD + k8 + t]);
                ah[ma][2] = __float_as_uint(AsH[r * LD + k8 + t + 4]);
                ah[ma][3] = __float_as_uint(AsH[(r + 8) * LD + k8 + t + 4]);
                al[ma][0] = __float_as_uint(AsL[r * LD + k8 + t]);
                al[ma][1] = __float_as_uint(AsL[(r + 8) * LD + k8 + t]);
                al[ma][2] = __float_as_uint(AsL[r * LD + k8 + t + 4]);
                al[ma][3] = __float_as_uint(AsL[(r + 8) * LD + k8 + t + 4]);
            }
#pragma unroll
            for (int nb = 0; nb < 4; nb++) {
                int n = wn * 32 + nb * 8 + g;
                bh[nb][0] = __float_as_uint(BsH[n * LD + k8 + t]);
                bh[nb][1] = __float_as_uint(BsH[n * LD + k8 + t + 4]);
                bl[nb][0] = __float_as_uint(BsL[n * LD + k8 + t]);
                bl[nb][1] = __float_as_uint(BsL[n * LD + k8 + t + 4]);
            }
#pragma unroll
            for (int ma = 0; ma < 2; ma++)
#pragma unroll
                for (int nb = 0; nb < 4; nb++) {
                    mma_m16n8k8(c[ma][nb], ah[ma], bh[nb]);
                    mma_m16n8k8(c[ma][nb], al[ma], bh[nb]);
                    mma_m16n8k8(c[ma][nb], ah[ma], bl[nb]);
                }
        }
    };

    const int NT = K >> 5;
    ldg_tile(0);
    __syncthreads();          // scaleS/shiftS visible (and smem reuse-safe)
    sts_tile(0);
    __syncthreads();
    for (int kt = 0; kt < NT; ++kt) {
        if (kt + 1 < NT) ldg_tile(kt + 1);   // LDGs in flight over MMA
        mma_chunk();
        __syncthreads();
        if (kt + 1 < NT) {
            sts_tile(kt + 1);
            __syncthreads();
        }
    }

    // epilogue: optional row scaling by dinv, store, optional fused col stats
#pragma unroll
    for (int ma = 0; ma < 2; ma++) {
        int r0 = m0 + wm * 32 + ma * 16 + g;
        float d0 = 1.f, d1 = 1.f;
        if (SCALE) {
            if (r0 < M) d0 = g_dinv[r0];
            if (r0 + 8 < M) d1 = g_dinv[r0 + 8];
        }
#pragma unroll
        for (int nb = 0; nb < 4; nb++) {
            int col = wn * 32 + nb * 8 + 2 * t;
            if (SCALE) {
                c[ma][nb][0] *= d0; c[ma][nb][1] *= d0;
                c[ma][nb][2] *= d1; c[ma][nb][3] *= d1;
            }
            if (r0 < M)
                *(float2*)(C + (size_t)r0 * BN + col) =
                    make_float2(c[ma][nb][0], c[ma][nb][1]);
            if (r0 + 8 < M)
                *(float2*)(C + (size_t)(r0 + 8) * BN + col) =
                    make_float2(c[ma][nb][2], c[ma][nb][3]);
        }
    }

    if (STATS) {
        float ps[4][2], pq[4][2];
#pragma unroll
        for (int nb = 0; nb < 4; nb++)
            ps[nb][0] = ps[nb][1] = pq[nb][0] = pq[nb][1] = 0.f;
#pragma unroll
        for (int ma = 0; ma < 2; ma++) {
            int r0 = m0 + wm * 32 + ma * 16 + g;
#pragma unroll
            for (int nb = 0; nb < 4; nb++) {
                if (r0 < M) {
                    ps[nb][0] += c[ma][nb][0]; pq[nb][0] += c[ma][nb][0] * c[ma][nb][0];
                    ps[nb][1] += c[ma][nb][1]; pq[nb][1] += c[ma][nb][1] * c[ma][nb][1];
                }
                if (r0 + 8 < M) {
                    ps[nb][0] += c[ma][nb][2]; pq[nb][0] += c[ma][nb][2] * c[ma][nb][2];
                    ps[nb][1] += c[ma][nb][3]; pq[nb][1] += c[ma][nb][3] * c[ma][nb][3];
                }
            }
        }
        // reduce over g (lane bits 2..4): lanes sharing t hold identical columns
#pragma unroll
        for (int off = 4; off <= 16; off <<= 1)
#pragma unroll
            for (int nb = 0; nb < 4; nb++)
#pragma unroll
                for (int j = 0; j < 2; j++) {
                    ps[nb][j] += __shfl_xor_sync(0xffffffffu, ps[nb][j], off);
                    pq[nb][j] += __shfl_xor_sync(0xffffffffu, pq[nb][j], off);
                }
        if (lane < 4) {
#pragma unroll
            for (int nb = 0; nb < 4; nb++)
#pragma unroll
                for (int j = 0; j < 2; j++) {
                    int col = wn * 32 + nb * 8 + 2 * t + j;
                    atomicAdd(&sumo[col], ps[nb][j]);
                    atomicAdd(&sqo[col], pq[nb][j]);
                }
        }
    }
}

static constexpr int smem_mma(int bn, bool fuse) {
    return (2 * 128 * 36 + 2 * bn * 36) * 4 + (fuse ? 1024 : 0);
}

// ---------------- prep: zero stats + indeg + all 4 weight transposes ------
// NOTE: grid must cover max(N, 512*128) threads (N=100000 > 65536).
__global__ void prep_kernel(const float* __restrict__ W1, const float* __restrict__ W2,
                            const float* __restrict__ Wg1, const float* __restrict__ Wg2,
                            int N) {
    int i = blockIdx.x * blockDim.x + threadIdx.x;
    if (i < 1024) ((float*)g_stats)[i] = 0.f;
    if (i < N) g_indeg[i] = 0;
    if (i < 512 * 128) { int k = i / 128, n = i % 128; g_wt1[n * 512 + k] = W1[i]; }
    if (i < 128 * 64)  { int k = i / 64,  n = i % 64;  g_wt2[n * 128 + k] = W2[i]; }
    if (i < 64 * 64)   { int k = i / 64,  n = i % 64;  g_wt3[n * 64 + k]  = Wg1[i]; }
    if (i < 64 * 32)   { int k = i / 32,  n = i % 32;  g_wt4[n * 64 + k]  = Wg2[i]; }
}

// ---------------- column stats (for agg outputs) ---------------------------
template <int C>
__global__ void colstats_kernel(const float* __restrict__ h, int M,
                                float* __restrict__ sumv, float* __restrict__ sqv) {
    int gtid = blockIdx.x * blockDim.x + threadIdx.x;
    int c = gtid & (C - 1);
    int r0 = gtid / C;
    int stride = (gridDim.x * blockDim.x) / C;
    float s = 0.f, q = 0.f;
    for (int r = r0; r < M; r += stride) {
        float v = h[(size_t)r * C + c];
        s += v;
        q += v * v;
    }
    atomicAdd(&sumv[c], s);
    atomicAdd(&sqv[c], q);
}

// ---------------- final BN apply (inline finalize) -> d_out ---------------
template <int C>
__global__ void bn_out_kernel(const float* __restrict__ in, float* __restrict__ out,
                              int M, const float* __restrict__ sumv,
                              const float* __restrict__ sqv,
                              const float* __restrict__ gamma,
                              const float* __restrict__ beta, float eps, float invM) {
    __shared__ float sc[C], sh[C];
    if (threadIdx.x < C) {
        float mean = sumv[threadIdx.x] * invM;
        float var = sqv[threadIdx.x] * invM - mean * mean;
        float s = gamma[threadIdx.x] * rsqrtf(var + eps);
        sc[threadIdx.x] = s;
        sh[threadIdx.x] = beta[threadIdx.x] - mean * s;
    }
    __syncthreads();
    int total4 = M * C / 4;
    for (int idx = blockIdx.x * blockDim.x + threadIdx.x; idx < total4;
         idx += gridDim.x * blockDim.x) {
        float4 v = ((const float4*)in)[idx];
        int c = (idx * 4) & (C - 1);
        ((float4*)out)[idx] = make_float4(v.x * sc[c + 0] + sh[c + 0],
                                          v.y * sc[c + 1] + sh[c + 1],
                                          v.z * sc[c + 2] + sh[c + 2],
                                          v.w * sc[c + 3] + sh[c + 3]);
    }
}

// ---------------- graph structure: degrees + CSR build --------------------
__global__ void count_kernel(const int* __restrict__ ei, int E) {
    int e = blockIdx.x * blockDim.x + threadIdx.x;
    if (e < E) atomicAdd(&g_indeg[ei[E + e]], 1);
}
__global__ void scan1_kernel(int N) {
    __shared__ int sh[1024];
    int tid = threadIdx.x;
    int i = blockIdx.x * 1024 + tid;
    int v = (i < N) ? g_indeg[i] : 0;
    sh[tid] = v;
    __syncthreads();
    for (int off = 1; off < 1024; off <<= 1) {
        int t = (tid >= off) ? sh[tid - off] : 0;
        __syncthreads();
        sh[tid] += t;
        __syncthreads();
    }
    if (i < N) g_rowptr[i] = sh[tid] - v;  // block-local exclusive
    if (tid == 1023) g_bsums[blockIdx.x] = sh[1023];
}
__global__ void scan2_kernel(int nb) {
    __shared__ int sh[256];
    int tid = threadIdx.x;
    int v = (tid < nb) ? g_bsums[tid] : 0;
    sh[tid] = v;
    __syncthreads();
    for (int off = 1; off < 256; off <<= 1) {
        int t = (tid >= off) ? sh[tid - off] : 0;
        __syncthreads();
        sh[tid] += t;
        __syncthreads();
    }
    if (tid < nb) g_bsums[tid] = sh[tid] - v;  // exclusive block offsets
}
__global__ void scan3_kernel(int N, int E) {   // also computes dinv
    int i = blockIdx.x * blockDim.x + threadIdx.x;
    if (i < N) {
        int v = g_rowptr[i] + g_bsums[i >> 10];
        g_rowptr[i] = v;
        g_cursor[i] = v;
        g_dinv[i] = rsqrtf((float)(g_indeg[i] + 1));  // +1 self loop
    }
    if (i == 0) g_rowptr[N] = E;
}
__global__ void fill_kernel(const int* __restrict__ ei, int E) {
    int e = blockIdx.x * blockDim.x + threadIdx.x;
    if (e < E) {
        int s = ei[e], d = ei[E + e];
        int p = atomicAdd(&g_cursor[d], 1);
        g_csrc[p] = s;
    }
}

// ---------------- GCN aggregation (inputs pre-scaled by dinv[src]) --------
// out[n] = dinv[n] * sum_{s in nbr(n) U {n}} hws[s]
template <int C>
__global__ void agg_kernel(const float* __restrict__ hws,
                           float* __restrict__ out, int N) {
    int warp = (blockIdx.x * blockDim.x + threadIdx.x) >> 5;
    int lane = threadIdx.x & 31;
    if (warp >= N) return;
    int n = warp;
    float dn = g_dinv[n];
    int start = g_rowptr[n];
    int end = g_rowptr[n + 1];

    if (C == 64) {
        float2 sv = *(const float2*)(hws + (size_t)n * 64 + lane * 2);
        float a0 = sv.x, a1 = sv.y;
        for (int i = start; i < end; i += 32) {
            int m = end - i;
            if (m > 32) m = 32;
            int s = (lane < m) ? g_csrc[i + lane] : 0;
#pragma unroll 4
            for (int j = 0; j < m; ++j) {
                int sj = __shfl_sync(0xffffffffu, s, j);
                float2 v = *(const float2*)(hws + (size_t)sj * 64 + lane * 2);
                a0 += v.x;
                a1 += v.y;
            }
        }
        *(float2*)(out + (size_t)n * 64 + lane * 2) = make_float2(dn * a0, dn * a1);
    } else {  // C == 32
        float a0 = hws[(size_t)n * 32 + lane];
        for (int i = start; i < end; i += 32) {
            int m = end - i;
            if (m > 32) m = 32;
            int s = (lane < m) ? g_csrc[i + lane] : 0;
#pragma unroll 4
            for (int j = 0; j < m; ++j) {
                int sj = __shfl_sync(0xffffffffu, s, j);
                a0 += hws[(size_t)sj * 32 + lane];
            }
        }
        out[(size_t)n * 32 + lane] = dn * a0;
    }
}

// ---------------- driver ---------------------------------------------------
extern "C" void kernel_launch(void* const* d_in, const int* in_sizes, int n_in,
                              void* d_out, int out_size) {
    const float* x   = (const float*)d_in[0];
    const int*   ei  = (const int*)d_in[1];
    const float* W1  = (const float*)d_in[2];
    const float* g1  = (const float*)d_in[4];
    const float* be1 = (const float*)d_in[5];
    const float* W2  = (const float*)d_in[6];
    const float* g2  = (const float*)d_in[8];
    const float* be2 = (const float*)d_in[9];
    const float* Wg1 = (const float*)d_in[10];
    const float* g3  = (const float*)d_in[12];
    const float* be3 = (const float*)d_in[13];
    const float* Wg2 = (const float*)d_in[14];
    const float* g4  = (const float*)d_in[16];
    const float* be4 = (const float*)d_in[17];
    // (all bias vectors are mathematically cancelled by batch-stat BN; skipped)

    const int N = in_sizes[0] / 512;
    const int E = in_sizes[1] / 2;
    const float invM = 1.f / (float)N;

    float *p_h1, *p_h2, *p_hw, *p_agg, *p_hw2, *p_agg2;
    float *p_wt1, *p_wt2, *p_wt3, *p_wt4, *p_st;
    cudaGetSymbolAddress((void**)&p_h1, g_h1);
    cudaGetSymbolAddress((void**)&p_h2, g_h2);
    cudaGetSymbolAddress((void**)&p_hw, g_hw);
    cudaGetSymbolAddress((void**)&p_agg, g_agg);
    cudaGetSymbolAddress((void**)&p_hw2, g_hw2);
    cudaGetSymbolAddress((void**)&p_agg2, g_agg2);
    cudaGetSymbolAddress((void**)&p_wt1, g_wt1);
    cudaGetSymbolAddress((void**)&p_wt2, g_wt2);
    cudaGetSymbolAddress((void**)&p_wt3, g_wt3);
    cudaGetSymbolAddress((void**)&p_wt4, g_wt4);
    cudaGetSymbolAddress((void**)&p_st, g_stats);
    float* s0 = p_st;        float* q0 = p_st + 128;
    float* s1 = p_st + 256;  float* q1 = p_st + 384;
    float* s2 = p_st + 512;  float* q2 = p_st + 640;
    float* s3 = p_st + 768;  float* q3 = p_st + 896;

    cudaFuncSetAttribute((void*)mma_gemm<128, 0, false, false, true>, cudaFuncAttributeMaxDynamicSharedMemorySize, smem_mma(128, false));
    cudaFuncSetAttribute((void*)mma_gemm<64, 1, true, false, true>,   cudaFuncAttributeMaxDynamicSharedMemorySize, smem_mma(64, true));
    cudaFuncSetAttribute((void*)mma_gemm<64, 1, true, true, false>,   cudaFuncAttributeMaxDynamicSharedMemorySize, smem_mma(64, true));
    cudaFuncSetAttribute((void*)mma_gemm<32, 2, true, true, false>,   cudaFuncAttributeMaxDynamicSharedMemorySize, smem_mma(32, true));

    const int nbN = (N + 255) / 256;
    const int nbE = (E + 255) / 256;
    const int nbScan = (N + 1023) / 1024;
    const int nbM = (N + 127) / 128;
    // prep must cover BOTH the N-element indeg zeroing and 512*128 transpose
    const int prepThreads = (N > 512 * 128) ? N : 512 * 128;
    const int nbPrep = (prepThreads + 255) / 256;

    // prep: zero stats + indeg + all weight transposes (one kernel)
    prep_kernel<<<nbPrep, 256>>>(W1, W2, Wg1, Wg2, N);

    // Graph structure (built once, reused by both GCN layers)
    count_kernel<<<nbE, 256>>>(ei, E);
    scan1_kernel<<<nbScan, 1024>>>(N);
    scan2_kernel<<<1, 256>>>(nbScan);
    scan3_kernel<<<nbN, 256>>>(N, E);
    fill_kernel<<<nbE, 256>>>(ei, E);

    // encoder_L1: Linear(512,128) + fused col stats; BN+ELU deferred to gemm2
    mma_gemm<128, 0, false, false, true><<<nbM, 512, smem_mma(128, false)>>>(
        x, p_wt1, p_h1, N, 512, nullptr, nullptr, nullptr, nullptr, 0.f, 0.f, s0, q0);

    // encoder_L2: A = ELU(BN(h1)) + fused col stats; BN+ELU of h2 -> gemm3
    mma_gemm<64, 1, true, false, true><<<nbM, 256, smem_mma(64, true)>>>(
        p_h1, p_wt2, p_h2, N, 128, s0, q0, g1, be1, 1e-3f, invM, s1, q1);

    // gc1: (ELU(BN(h2)) @ Wg1) * dinv[row], then plain-sum aggregate
    mma_gemm<64, 1, true, true, false><<<nbM, 256, smem_mma(64, true)>>>(
        p_h2, p_wt3, p_hw, N, 64, s1, q1, g2, be2, 1e-3f, invM, nullptr, nullptr);
    agg_kernel<64><<<(N * 32 + 255) / 256, 256>>>(p_hw, p_agg, N);
    colstats_kernel<64><<<128, 256>>>(p_agg, N, s2, q2);

    // gc2: A = ReLU(BN(agg)), output * dinv[row]; aggregate; final BN -> d_out
    mma_gemm<32, 2, true, true, false><<<nbM, 128, smem_mma(32, true)>>>(
        p_agg, p_wt4, p_hw2, N, 64, s2, q2, g3, be3, 1e-5f, invM, nullptr, nullptr);
    agg_kernel<32><<<(N * 32 + 255) / 256, 256>>>(p_hw2, p_agg2, N);
    colstats_kernel<32><<<128, 256>>>(p_agg2, N, s3, q3);
    bn_out_kernel<32><<<512, 256>>>(p_agg2, (float*)d_out, N, s3, q3, g4, be4,
                                    1e-5f, invM);
}

// round 15
// speedup vs baseline: 2.6866x; 1.1095x over previous
#include <cuda_runtime.h>
#include <math.h>
#include <cstdint>

#define MAXN 100000
#define MAXE 3200000

// ---------------- device scratch (no allocations allowed) ----------------
__device__ float g_h1[MAXN * 128];
__device__ float g_h2[MAXN * 64];
__device__ float g_hw[MAXN * 64];
__device__ float g_agg[MAXN * 64];
__device__ float g_hw2[MAXN * 32];
__device__ float g_agg2[MAXN * 32];
__device__ float g_wt1[512 * 128];
__device__ float g_wt2[128 * 64];
__device__ float g_wt3[64 * 64];
__device__ float g_wt4[64 * 32];
__device__ float g_stats[4][2][128];       // per-layer raw col sum / sumsq
__device__ int   g_indeg[MAXN];
__device__ float g_dinv[MAXN];
__device__ int   g_rowptr[MAXN + 1];
__device__ int   g_cursor[MAXN];
__device__ int   g_csrc[MAXE];
__device__ int   g_bsums[256];

// ---------------- bf16 split helpers (sm_80+ PTX, valid on sm_103) --------
// pack two floats into a bf16x2 word: lo half = first arg, hi half = second
__device__ __forceinline__ uint32_t pack2(float vlo, float vhi) {
    uint32_t r;
    asm("cvt.rn.bf16x2.f32 %0, %1, %2;" : "=r"(r) : "f"(vhi), "f"(vlo));
    return r;
}
__device__ __forceinline__ float lo_f(uint32_t u) { return __uint_as_float(u << 16); }
__device__ __forceinline__ float hi_f(uint32_t u) { return __uint_as_float(u & 0xffff0000u); }

__device__ __forceinline__ void mma_bf16(float* c, const uint32_t* a,
                                         const uint32_t* b) {
    asm volatile(
        "mma.sync.aligned.m16n8k16.row.col.f32.bf16.bf16.f32 "
        "{%0,%1,%2,%3}, {%4,%5,%6,%7}, {%8,%9}, {%0,%1,%2,%3};"
        : "+f"(c[0]), "+f"(c[1]), "+f"(c[2]), "+f"(c[3])
        : "r"(a[0]), "r"(a[1]), "r"(a[2]), "r"(a[3]), "r"(b[0]), "r"(b[1]));
}

__device__ __forceinline__ float act_f(float t, int ACT) {
    if (ACT == 1) return (t > 0.f) ? t : expm1f(t);
    if (ACT == 2) return (t > 0.f) ? t : 0.f;
    return t;
}

// ---------------- tensor-core split-bf16 GEMM: C = A'[M,K] @ Bt[BN,K]^T ---
// 3-term bf16 split (Ah*Bh + Al*Bh + Ah*Bl); dropped term ~2^-18 relative.
// A' = act(A*scale + shift) when FUSE. SCALE: out row r *= g_dinv[r].
// STATS: fused column sum/sumsq of C via warp-reduced atomics.
// BM=128 per CTA, warp tile 32x32, K chunked by 32 (2 x k16 MMA steps),
// bf16 smem rows LD=40 (conflict-free frag LDS), register-staged dbl buffer.
template <int BN, int ACT, bool FUSE, bool SCALE, bool STATS>
__global__ void __launch_bounds__(BN * 4)
mma_gemm(const float* __restrict__ A, const float* __restrict__ Bt,
         float* __restrict__ C, int M, int K,
         const float* __restrict__ sumv, const float* __restrict__ sqv,
         const float* __restrict__ gamma, const float* __restrict__ beta,
         float eps, float invM,
         float* __restrict__ sumo, float* __restrict__ sqo) {
    constexpr int LD = 40;           // bf16 units/row: bank=(20r+t)%32 distinct
    constexpr int T  = BN * 4;       // threads
    constexpr int NWN = BN / 32;     // warps along N
    constexpr int APT = 1024 / T;    // A float4s per thread per chunk
    extern __shared__ char smc[];
    uint16_t* AsH = (uint16_t*)smc;            // 128 x LD
    uint16_t* AsL = AsH + 128 * LD;
    uint16_t* BsH = AsL + 128 * LD;            // BN x LD
    uint16_t* BsL = BsH + BN * LD;
    float* scaleS = (float*)(BsL + BN * LD);   // [128] (only when FUSE)
    float* shiftS = scaleS + 128;

    const int tid = threadIdx.x;
    const int wid = tid >> 5, lane = tid & 31;
    const int wm = wid / NWN, wn = wid % NWN;
    const int g = lane >> 2, t = lane & 3;
    const int m0 = blockIdx.x * 128;

    if (FUSE) {
        for (int c = tid; c < K; c += T) {
            float mean = sumv[c] * invM;
            float var = sqv[c] * invM - mean * mean;
            float sc = gamma[c] * rsqrtf(var + eps);
            scaleS[c] = sc;
            shiftS[c] = beta[c] - mean * sc;
        }
    }

    float c[2][4][4];
#pragma unroll
    for (int i = 0; i < 2; i++)
#pragma unroll
        for (int j = 0; j < 4; j++)
#pragma unroll
            for (int k = 0; k < 4; k++) c[i][j][k] = 0.f;

    float4 aReg[APT], bReg[2];

    auto ldg_tile = [&](int kt) {
#pragma unroll
        for (int i = 0; i < APT; i++) {
            int f = tid + i * T;
            int row = f >> 3, c4 = f & 7;
            aReg[i] = make_float4(0.f, 0.f, 0.f, 0.f);
            if (m0 + row < M)
                aReg[i] = *(const float4*)(A + (size_t)(m0 + row) * K + kt * 32 + c4 * 4);
        }
#pragma unroll
        for (int i = 0; i < 2; i++) {
            int f = tid + i * T;
            int row = f >> 3, c4 = f & 7;
            bReg[i] = *(const float4*)(Bt + (size_t)row * K + kt * 32 + c4 * 4);
        }
    };
    auto split_sts = [&](uint16_t* H, uint16_t* L, int row, int c4, float4 v) {
        uint32_t h0 = pack2(v.x, v.y);
        uint32_t h1 = pack2(v.z, v.w);
        float l0 = v.x - lo_f(h0), l1 = v.y - hi_f(h0);
        float l2 = v.z - lo_f(h1), l3 = v.w - hi_f(h1);
        uint32_t L0 = pack2(l0, l1);
        uint32_t L1 = pack2(l2, l3);
        *(uint2*)(H + row * LD + c4 * 4) = make_uint2(h0, h1);
        *(uint2*)(L + row * LD + c4 * 4) = make_uint2(L0, L1);
    };
    auto sts_tile = [&](int kt) {
#pragma unroll
        for (int i = 0; i < APT; i++) {
            int f = tid + i * T;
            int row = f >> 3, c4 = f & 7;
            float4 v = aReg[i];
            if (FUSE) {
                int cb = kt * 32 + c4 * 4;
                v.x = act_f(v.x * scaleS[cb + 0] + shiftS[cb + 0], ACT);
                v.y = act_f(v.y * scaleS[cb + 1] + shiftS[cb + 1], ACT);
                v.z = act_f(v.z * scaleS[cb + 2] + shiftS[cb + 2], ACT);
                v.w = act_f(v.w * scaleS[cb + 3] + shiftS[cb + 3], ACT);
            }
            split_sts(AsH, AsL, row, c4, v);
        }
#pragma unroll
        for (int i = 0; i < 2; i++) {
            int f = tid + i * T;
            int row = f >> 3, c4 = f & 7;
            split_sts(BsH, BsL, row, c4, bReg[i]);
        }
    };
    auto mma_chunk = [&]() {
#pragma unroll
        for (int ks = 0; ks < 2; ++ks) {
            const int k16 = ks * 16;          // bf16-unit col offset
            uint32_t ah[2][4], al[2][4], bh[4][2], bl[4][2];
#pragma unroll
            for (int ma = 0; ma < 2; ma++) {
                int r = wm * 32 + ma * 16 + g;
                ah[ma][0] = *(const uint32_t*)(AsH + r * LD + k16 + 2 * t);
                ah[ma][1] = *(const uint32_t*)(AsH + (r + 8) * LD + k16 + 2 * t);
                ah[ma][2] = *(const uint32_t*)(AsH + r * LD + k16 + 2 * t + 8);
                ah[ma][3] = *(const uint32_t*)(AsH + (r + 8) * LD + k16 + 2 * t + 8);
                al[ma][0] = *(const uint32_t*)(AsL + r * LD + k16 + 2 * t);
                al[ma][1] = *(const uint32_t*)(AsL + (r + 8) * LD + k16 + 2 * t);
                al[ma][2] = *(const uint32_t*)(AsL + r * LD + k16 + 2 * t + 8);
                al[ma][3] = *(const uint32_t*)(AsL + (r + 8) * LD + k16 + 2 * t + 8);
            }
#pragma unroll
            for (int nb = 0; nb < 4; nb++) {
                int n = wn * 32 + nb * 8 + g;
                bh[nb][0] = *(const uint32_t*)(BsH + n * LD + k16 + 2 * t);
                bh[nb][1] = *(const uint32_t*)(BsH + n * LD + k16 + 2 * t + 8);
                bl[nb][0] = *(const uint32_t*)(BsL + n * LD + k16 + 2 * t);
                bl[nb][1] = *(const uint32_t*)(BsL + n * LD + k16 + 2 * t + 8);
            }
#pragma unroll
            for (int ma = 0; ma < 2; ma++)
#pragma unroll
                for (int nb = 0; nb < 4; nb++) {
                    mma_bf16(c[ma][nb], ah[ma], bh[nb]);
                    mma_bf16(c[ma][nb], al[ma], bh[nb]);
                    mma_bf16(c[ma][nb], ah[ma], bl[nb]);
                }
        }
    };

    const int NT = K >> 5;
    ldg_tile(0);
    __syncthreads();          // scaleS/shiftS visible (and smem reuse-safe)
    sts_tile(0);
    __syncthreads();
    for (int kt = 0; kt < NT; ++kt) {
        if (kt + 1 < NT) ldg_tile(kt + 1);   // LDGs in flight over MMA
        mma_chunk();
        __syncthreads();
        if (kt + 1 < NT) {
            sts_tile(kt + 1);
            __syncthreads();
        }
    }

    // epilogue: optional row scaling by dinv, store, optional fused col stats
#pragma unroll
    for (int ma = 0; ma < 2; ma++) {
        int r0 = m0 + wm * 32 + ma * 16 + g;
        float d0 = 1.f, d1 = 1.f;
        if (SCALE) {
            if (r0 < M) d0 = g_dinv[r0];
            if (r0 + 8 < M) d1 = g_dinv[r0 + 8];
        }
#pragma unroll
        for (int nb = 0; nb < 4; nb++) {
            int col = wn * 32 + nb * 8 + 2 * t;
            if (SCALE) {
                c[ma][nb][0] *= d0; c[ma][nb][1] *= d0;
                c[ma][nb][2] *= d1; c[ma][nb][3] *= d1;
            }
            if (r0 < M)
                *(float2*)(C + (size_t)r0 * BN + col) =
                    make_float2(c[ma][nb][0], c[ma][nb][1]);
            if (r0 + 8 < M)
                *(float2*)(C + (size_t)(r0 + 8) * BN + col) =
                    make_float2(c[ma][nb][2], c[ma][nb][3]);
        }
    }

    if (STATS) {
        float ps[4][2], pq[4][2];
#pragma unroll
        for (int nb = 0; nb < 4; nb++)
            ps[nb][0] = ps[nb][1] = pq[nb][0] = pq[nb][1] = 0.f;
#pragma unroll
        for (int ma = 0; ma < 2; ma++) {
            int r0 = m0 + wm * 32 + ma * 16 + g;
#pragma unroll
            for (int nb = 0; nb < 4; nb++) {
                if (r0 < M) {
                    ps[nb][0] += c[ma][nb][0]; pq[nb][0] += c[ma][nb][0] * c[ma][nb][0];
                    ps[nb][1] += c[ma][nb][1]; pq[nb][1] += c[ma][nb][1] * c[ma][nb][1];
                }
                if (r0 + 8 < M) {
                    ps[nb][0] += c[ma][nb][2]; pq[nb][0] += c[ma][nb][2] * c[ma][nb][2];
                    ps[nb][1] += c[ma][nb][3]; pq[nb][1] += c[ma][nb][3] * c[ma][nb][3];
                }
            }
        }
        // reduce over g (lane bits 2..4): lanes sharing t hold identical columns
#pragma unroll
        for (int off = 4; off <= 16; off <<= 1)
#pragma unroll
            for (int nb = 0; nb < 4; nb++)
#pragma unroll
                for (int j = 0; j < 2; j++) {
                    ps[nb][j] += __shfl_xor_sync(0xffffffffu, ps[nb][j], off);
                    pq[nb][j] += __shfl_xor_sync(0xffffffffu, pq[nb][j], off);
                }
        if (lane < 4) {
#pragma unroll
            for (int nb = 0; nb < 4; nb++)
#pragma unroll
                for (int j = 0; j < 2; j++) {
                    int col = wn * 32 + nb * 8 + 2 * t + j;
                    atomicAdd(&sumo[col], ps[nb][j]);
                    atomicAdd(&sqo[col], pq[nb][j]);
                }
        }
    }
}

static constexpr int smem_mma(int bn, bool fuse) {
    return (2 * 128 + 2 * bn) * 40 * 2 + (fuse ? 1024 : 0);
}

// ---------------- prep: zero stats + indeg + all 4 weight transposes ------
// NOTE: grid must cover max(N, 512*128) threads (N=100000 > 65536).
__global__ void prep_kernel(const float* __restrict__ W1, const float* __restrict__ W2,
                            const float* __restrict__ Wg1, const float* __restrict__ Wg2,
                            int N) {
    int i = blockIdx.x * blockDim.x + threadIdx.x;
    if (i < 1024) ((float*)g_stats)[i] = 0.f;
    if (i < N) g_indeg[i] = 0;
    if (i < 512 * 128) { int k = i / 128, n = i % 128; g_wt1[n * 512 + k] = W1[i]; }
    if (i < 128 * 64)  { int k = i / 64,  n = i % 64;  g_wt2[n * 128 + k] = W2[i]; }
    if (i < 64 * 64)   { int k = i / 64,  n = i % 64;  g_wt3[n * 64 + k]  = Wg1[i]; }
    if (i < 64 * 32)   { int k = i / 32,  n = i % 32;  g_wt4[n * 64 + k]  = Wg2[i]; }
}

// ---------------- final BN apply (inline finalize) -> d_out ---------------
template <int C>
__global__ void bn_out_kernel(const float* __restrict__ in, float* __restrict__ out,
                              int M, const float* __restrict__ sumv,
                              const float* __restrict__ sqv,
                              const float* __restrict__ gamma,
                              const float* __restrict__ beta, float eps, float invM) {
    __shared__ float sc[C], sh[C];
    if (threadIdx.x < C) {
        float mean = sumv[threadIdx.x] * invM;
        float var = sqv[threadIdx.x] * invM - mean * mean;
        float s = gamma[threadIdx.x] * rsqrtf(var + eps);
        sc[threadIdx.x] = s;
        sh[threadIdx.x] = beta[threadIdx.x] - mean * s;
    }
    __syncthreads();
    int total4 = M * C / 4;
    for (int idx = blockIdx.x * blockDim.x + threadIdx.x; idx < total4;
         idx += gridDim.x * blockDim.x) {
        float4 v = ((const float4*)in)[idx];
        int c = (idx * 4) & (C - 1);
        ((float4*)out)[idx] = make_float4(v.x * sc[c + 0] + sh[c + 0],
                                          v.y * sc[c + 1] + sh[c + 1],
                                          v.z * sc[c + 2] + sh[c + 2],
                                          v.w * sc[c + 3] + sh[c + 3]);
    }
}

// ---------------- graph structure: degrees + CSR build --------------------
__global__ void count_kernel(const int* __restrict__ ei, int E) {
    int e = blockIdx.x * blockDim.x + threadIdx.x;
    if (e < E) atomicAdd(&g_indeg[ei[E + e]], 1);
}
__global__ void scan1_kernel(int N) {
    __shared__ int sh[1024];
    int tid = threadIdx.x;
    int i = blockIdx.x * 1024 + tid;
    int v = (i < N) ? g_indeg[i] : 0;
    sh[tid] = v;
    __syncthreads();
    for (int off = 1; off < 1024; off <<= 1) {
        int t = (tid >= off) ? sh[tid - off] : 0;
        __syncthreads();
        sh[tid] += t;
        __syncthreads();
    }
    if (i < N) g_rowptr[i] = sh[tid] - v;  // block-local exclusive
    if (tid == 1023) g_bsums[blockIdx.x] = sh[1023];
}
__global__ void scan2_kernel(int nb) {
    __shared__ int sh[256];
    int tid = threadIdx.x;
    int v = (tid < nb) ? g_bsums[tid] : 0;
    sh[tid] = v;
    __syncthreads();
    for (int off = 1; off < 256; off <<= 1) {
        int t = (tid >= off) ? sh[tid - off] : 0;
        __syncthreads();
        sh[tid] += t;
        __syncthreads();
    }
    if (tid < nb) g_bsums[tid] = sh[tid] - v;  // exclusive block offsets
}
__global__ void scan3_kernel(int N, int E) {   // also computes dinv
    int i = blockIdx.x * blockDim.x + threadIdx.x;
    if (i < N) {
        int v = g_rowptr[i] + g_bsums[i >> 10];
        g_rowptr[i] = v;
        g_cursor[i] = v;
        g_dinv[i] = rsqrtf((float)(g_indeg[i] + 1));  // +1 self loop
    }
    if (i == 0) g_rowptr[N] = E;
}
__global__ void fill_kernel(const int* __restrict__ ei, int E) {
    int e = blockIdx.x * blockDim.x + threadIdx.x;
    if (e < E) {
        int s = ei[e], d = ei[E + e];
        int p = atomicAdd(&g_cursor[d], 1);
        g_csrc[p] = s;
    }
}

// ---------------- GCN aggregation (inputs pre-scaled by dinv[src]) --------
// out[n] = dinv[n] * sum_{s in nbr(n) U {n}} hws[s]; optional fused col stats.
// No early return: inactive warps must reach the block barriers.
template <int C, bool STATS>
__global__ void agg_kernel(const float* __restrict__ hws,
                           float* __restrict__ out, int N,
                           float* __restrict__ sumv, float* __restrict__ sqv) {
    __shared__ float ssum[C], ssq[C];
    int tid = threadIdx.x;
    if (STATS) {
        if (tid < C) { ssum[tid] = 0.f; ssq[tid] = 0.f; }
        __syncthreads();
    }
    int warp = (blockIdx.x * blockDim.x + tid) >> 5;
    int lane = tid & 31;
    bool active = warp < N;
    int n = active ? warp : 0;

    if (C == 64) {
        float a0 = 0.f, a1 = 0.f, dn = 0.f;
        if (active) {
            dn = g_dinv[n];
            float2 sv = *(const float2*)(hws + (size_t)n * 64 + lane * 2);
            a0 = sv.x; a1 = sv.y;
            int start = g_rowptr[n], end = g_rowptr[n + 1];
            for (int i = start; i < end; i += 32) {
                int m = end - i;
                if (m > 32) m = 32;
                int s = (lane < m) ? g_csrc[i + lane] : 0;
#pragma unroll 4
                for (int j = 0; j < m; ++j) {
                    int sj = __shfl_sync(0xffffffffu, s, j);
                    float2 v = *(const float2*)(hws + (size_t)sj * 64 + lane * 2);
                    a0 += v.x;
                    a1 += v.y;
                }
            }
            a0 *= dn; a1 *= dn;
            *(float2*)(out + (size_t)n * 64 + lane * 2) = make_float2(a0, a1);
        }
        if (STATS) {
            if (active) {
                atomicAdd(&ssum[2 * lane], a0);
                atomicAdd(&ssum[2 * lane + 1], a1);
                atomicAdd(&ssq[2 * lane], a0 * a0);
                atomicAdd(&ssq[2 * lane + 1], a1 * a1);
            }
            __syncthreads();
            if (tid < C) {
                atomicAdd(&sumv[tid], ssum[tid]);
                atomicAdd(&sqv[tid], ssq[tid]);
            }
        }
    } else {  // C == 32
        float a0 = 0.f;
        if (active) {
            float dn = g_dinv[n];
            a0 = hws[(size_t)n * 32 + lane];
            int start = g_rowptr[n], end = g_rowptr[n + 1];
            for (int i = start; i < end; i += 32) {
                int m = end - i;
                if (m > 32) m = 32;
                int s = (lane < m) ? g_csrc[i + lane] : 0;
#pragma unroll 4
                for (int j = 0; j < m; ++j) {
                    int sj = __shfl_sync(0xffffffffu, s, j);
                    a0 += hws[(size_t)sj * 32 + lane];
                }
            }
            a0 *= dn;
            out[(size_t)n * 32 + lane] = a0;
        }
        if (STATS) {
            if (active) {
                atomicAdd(&ssum[lane], a0);
                atomicAdd(&ssq[lane], a0 * a0);
            }
            __syncthreads();
            if (tid < C) {
                atomicAdd(&sumv[tid], ssum[tid]);
                atomicAdd(&sqv[tid], ssq[tid]);
            }
        }
    }
}

// ---------------- driver ---------------------------------------------------
extern "C" void kernel_launch(void* const* d_in, const int* in_sizes, int n_in,
                              void* d_out, int out_size) {
    const float* x   = (const float*)d_in[0];
    const int*   ei  = (const int*)d_in[1];
    const float* W1  = (const float*)d_in[2];
    const float* g1  = (const float*)d_in[4];
    const float* be1 = (const float*)d_in[5];
    const float* W2  = (const float*)d_in[6];
    const float* g2  = (const float*)d_in[8];
    const float* be2 = (const float*)d_in[9];
    const float* Wg1 = (const float*)d_in[10];
    const float* g3  = (const float*)d_in[12];
    const float* be3 = (const float*)d_in[13];
    const float* Wg2 = (const float*)d_in[14];
    const float* g4  = (const float*)d_in[16];
    const float* be4 = (const float*)d_in[17];
    // (all bias vectors are mathematically cancelled by batch-stat BN; skipped)

    const int N = in_sizes[0] / 512;
    const int E = in_sizes[1] / 2;
    const float invM = 1.f / (float)N;

    float *p_h1, *p_h2, *p_hw, *p_agg, *p_hw2, *p_agg2;
    float *p_wt1, *p_wt2, *p_wt3, *p_wt4, *p_st;
    cudaGetSymbolAddress((void**)&p_h1, g_h1);
    cudaGetSymbolAddress((void**)&p_h2, g_h2);
    cudaGetSymbolAddress((void**)&p_hw, g_hw);
    cudaGetSymbolAddress((void**)&p_agg, g_agg);
    cudaGetSymbolAddress((void**)&p_hw2, g_hw2);
    cudaGetSymbolAddress((void**)&p_agg2, g_agg2);
    cudaGetSymbolAddress((void**)&p_wt1, g_wt1);
    cudaGetSymbolAddress((void**)&p_wt2, g_wt2);
    cudaGetSymbolAddress((void**)&p_wt3, g_wt3);
    cudaGetSymbolAddress((void**)&p_wt4, g_wt4);
    cudaGetSymbolAddress((void**)&p_st, g_stats);
    float* s0 = p_st;        float* q0 = p_st + 128;
    float* s1 = p_st + 256;  float* q1 = p_st + 384;
    float* s2 = p_st + 512;  float* q2 = p_st + 640;
    float* s3 = p_st + 768;  float* q3 = p_st + 896;

    cudaFuncSetAttribute((void*)mma_gemm<128, 0, false, false, true>, cudaFuncAttributeMaxDynamicSharedMemorySize, smem_mma(128, false));
    cudaFuncSetAttribute((void*)mma_gemm<64, 1, true, false, true>,   cudaFuncAttributeMaxDynamicSharedMemorySize, smem_mma(64, true));
    cudaFuncSetAttribute((void*)mma_gemm<64, 1, true, true, false>,   cudaFuncAttributeMaxDynamicSharedMemorySize, smem_mma(64, true));
    cudaFuncSetAttribute((void*)mma_gemm<32, 2, true, true, false>,   cudaFuncAttributeMaxDynamicSharedMemorySize, smem_mma(32, true));

    const int nbN = (N + 255) / 256;
    const int nbE = (E + 255) / 256;
    const int nbScan = (N + 1023) / 1024;
    const int nbM = (N + 127) / 128;
    // prep must cover BOTH the N-element indeg zeroing and 512*128 transpose
    const int prepThreads = (N > 512 * 128) ? N : 512 * 128;
    const int nbPrep = (prepThreads + 255) / 256;

    // prep: zero stats + indeg + all weight transposes (one kernel)
    prep_kernel<<<nbPrep, 256>>>(W1, W2, Wg1, Wg2, N);

    // Graph structure (built once, reused by both GCN layers)
    count_kernel<<<nbE, 256>>>(ei, E);
    scan1_kernel<<<nbScan, 1024>>>(N);
    scan2_kernel<<<1, 256>>>(nbScan);
    scan3_kernel<<<nbN, 256>>>(N, E);
    fill_kernel<<<nbE, 256>>>(ei, E);

    // encoder_L1: Linear(512,128) + fused col stats; BN+ELU deferred to gemm2
    mma_gemm<128, 0, false, false, true><<<nbM, 512, smem_mma(128, false)>>>(
        x, p_wt1, p_h1, N, 512, nullptr, nullptr, nullptr, nullptr, 0.f, 0.f, s0, q0);

    // encoder_L2: A = ELU(BN(h1)) + fused col stats; BN+ELU of h2 -> gemm3
    mma_gemm<64, 1, true, false, true><<<nbM, 256, smem_mma(64, true)>>>(
        p_h1, p_wt2, p_h2, N, 128, s0, q0, g1, be1, 1e-3f, invM, s1, q1);

    // gc1: (ELU(BN(h2)) @ Wg1) * dinv[row]; aggregate + fused col stats
    mma_gemm<64, 1, true, true, false><<<nbM, 256, smem_mma(64, true)>>>(
        p_h2, p_wt3, p_hw, N, 64, s1, q1, g2, be2, 1e-3f, invM, nullptr, nullptr);
    agg_kernel<64, true><<<(N * 32 + 255) / 256, 256>>>(p_hw, p_agg, N, s2, q2);

    // gc2: A = ReLU(BN(agg)), output * dinv[row]; aggregate + stats; BN -> d_out
    mma_gemm<32, 2, true, true, false><<<nbM, 128, smem_mma(32, true)>>>(
        p_agg, p_wt4, p_hw2, N, 64, s2, q2, g3, be3, 1e-5f, invM, nullptr, nullptr);
    agg_kernel<32, true><<<(N * 32 + 255) / 256, 256>>>(p_hw2, p_agg2, N, s3, q3);
    bn_out_kernel<32><<<512, 256>>>(p_agg2, (float*)d_out, N, s3, q3, g4, be4,
                                    1e-5f, invM);
}

// round 17
// speedup vs baseline: 2.9149x; 1.0850x over previous
#include <cuda_runtime.h>
#include <math.h>
#include <cstdint>

#define MAXN 100000
#define MAXE 3200000

// ---------------- device scratch (no allocations allowed) ----------------
__device__ float g_h1[MAXN * 128];
__device__ float g_h2[MAXN * 64];
__device__ float g_hw[MAXN * 64];
__device__ float g_agg[MAXN * 64];
__device__ float g_hw2[MAXN * 32];
__device__ float g_agg2[MAXN * 32];
__device__ float g_wt1[512 * 128];
__device__ float g_wt2[128 * 64];
__device__ float g_wt3[64 * 64];
__device__ float g_wt4[64 * 32];
__device__ float g_stats[4][2][128];       // per-layer raw col sum / sumsq
__device__ int   g_indeg[MAXN];
__device__ float g_dinv[MAXN];
__device__ int   g_rowptr[MAXN + 1];
__device__ int   g_cursor[MAXN];
__device__ int   g_csrc[MAXE];
__device__ int   g_bsums[256];

// ---------------- bf16 split helpers (sm_80+ PTX, valid on sm_103) --------
// pack two floats into a bf16x2 word: lo half = first arg, hi half = second
__device__ __forceinline__ uint32_t pack2(float vlo, float vhi) {
    uint32_t r;
    asm("cvt.rn.bf16x2.f32 %0, %1, %2;" : "=r"(r) : "f"(vhi), "f"(vlo));
    return r;
}
__device__ __forceinline__ float lo_f(uint32_t u) { return __uint_as_float(u << 16); }
__device__ __forceinline__ float hi_f(uint32_t u) { return __uint_as_float(u & 0xffff0000u); }

__device__ __forceinline__ void mma_bf16(float* c, const uint32_t* a,
                                         const uint32_t* b) {
    asm volatile(
        "mma.sync.aligned.m16n8k16.row.col.f32.bf16.bf16.f32 "
        "{%0,%1,%2,%3}, {%4,%5,%6,%7}, {%8,%9}, {%0,%1,%2,%3};"
        : "+f"(c[0]), "+f"(c[1]), "+f"(c[2]), "+f"(c[3])
        : "r"(a[0]), "r"(a[1]), "r"(a[2]), "r"(a[3]), "r"(b[0]), "r"(b[1]));
}

__device__ __forceinline__ float act_f(float t, int ACT) {
    if (ACT == 1) return (t > 0.f) ? t : expm1f(t);
    if (ACT == 2) return (t > 0.f) ? t : 0.f;
    return t;
}

// ---------------- tensor-core split-bf16 GEMM: C = A'[M,K] @ Bt[BN,K]^T ---
// 3-term bf16 split (Ah*Bh + Al*Bh + Ah*Bl); dropped term ~2^-18 relative.
// A' = act(A*scale + shift) when FUSE. SCALE: out row r *= g_dinv[r].
// STATS: fused column sum/sumsq of C via warp-reduced atomics.
// BM=128 per CTA, warp tile 32x32, K chunked by 32 (2 x k16 MMA steps),
// bf16 smem rows LD=40 (conflict-free frag LDS).
// DOUBLE-BUFFERED smem: one __syncthreads per chunk; next chunk's STS
// overlaps other warps' MMA on the other buffer.
template <int BN, int ACT, bool FUSE, bool SCALE, bool STATS>
__global__ void __launch_bounds__(BN * 4)
mma_gemm(const float* __restrict__ A, const float* __restrict__ Bt,
         float* __restrict__ C, int M, int K,
         const float* __restrict__ sumv, const float* __restrict__ sqv,
         const float* __restrict__ gamma, const float* __restrict__ beta,
         float eps, float invM,
         float* __restrict__ sumo, float* __restrict__ sqo) {
    constexpr int LD = 40;           // bf16 units/row: bank=(20r+t)%32 distinct
    constexpr int T  = BN * 4;       // threads
    constexpr int NWN = BN / 32;     // warps along N
    constexpr int APT = 1024 / T;    // A float4s per thread per chunk
    constexpr int TSA = 128 * LD;    // per-buffer A tile (uint16 units)
    constexpr int TSB = BN * LD;     // per-buffer B tile
    extern __shared__ char smc[];
    uint16_t* AsH = (uint16_t*)smc;            // 2 buffers each
    uint16_t* AsL = AsH + 2 * TSA;
    uint16_t* BsH = AsL + 2 * TSA;
    uint16_t* BsL = BsH + 2 * TSB;
    float* scaleS = (float*)(BsL + 2 * TSB);   // [128] (only when FUSE)
    float* shiftS = scaleS + 128;

    const int tid = threadIdx.x;
    const int wid = tid >> 5, lane = tid & 31;
    const int wm = wid / NWN, wn = wid % NWN;
    const int g = lane >> 2, t = lane & 3;
    const int m0 = blockIdx.x * 128;

    if (FUSE) {
        for (int c = tid; c < K; c += T) {
            float mean = sumv[c] * invM;
            float var = sqv[c] * invM - mean * mean;
            float sc = gamma[c] * rsqrtf(var + eps);
            scaleS[c] = sc;
            shiftS[c] = beta[c] - mean * sc;
        }
    }

    float c[2][4][4];
#pragma unroll
    for (int i = 0; i < 2; i++)
#pragma unroll
        for (int j = 0; j < 4; j++)
#pragma unroll
            for (int k = 0; k < 4; k++) c[i][j][k] = 0.f;

    float4 aReg[APT], bReg[2];

    auto ldg_tile = [&](int kt) {
#pragma unroll
        for (int i = 0; i < APT; i++) {
            int f = tid + i * T;
            int row = f >> 3, c4 = f & 7;
            aReg[i] = make_float4(0.f, 0.f, 0.f, 0.f);
            if (m0 + row < M)
                aReg[i] = *(const float4*)(A + (size_t)(m0 + row) * K + kt * 32 + c4 * 4);
        }
#pragma unroll
        for (int i = 0; i < 2; i++) {
            int f = tid + i * T;
            int row = f >> 3, c4 = f & 7;
            bReg[i] = *(const float4*)(Bt + (size_t)row * K + kt * 32 + c4 * 4);
        }
    };
    auto split_sts = [&](uint16_t* H, uint16_t* L, int row, int c4, float4 v) {
        uint32_t h0 = pack2(v.x, v.y);
        uint32_t h1 = pack2(v.z, v.w);
        float l0 = v.x - lo_f(h0), l1 = v.y - hi_f(h0);
        float l2 = v.z - lo_f(h1), l3 = v.w - hi_f(h1);
        uint32_t L0 = pack2(l0, l1);
        uint32_t L1 = pack2(l2, l3);
        *(uint2*)(H + row * LD + c4 * 4) = make_uint2(h0, h1);
        *(uint2*)(L + row * LD + c4 * 4) = make_uint2(L0, L1);
    };
    auto sts_tile = [&](int kt, int buf) {
        uint16_t* aH = AsH + buf * TSA;
        uint16_t* aL = AsL + buf * TSA;
        uint16_t* bH = BsH + buf * TSB;
        uint16_t* bL = BsL + buf * TSB;
#pragma unroll
        for (int i = 0; i < APT; i++) {
            int f = tid + i * T;
            int row = f >> 3, c4 = f & 7;
            float4 v = aReg[i];
            if (FUSE) {
                int cb = kt * 32 + c4 * 4;
                v.x = act_f(v.x * scaleS[cb + 0] + shiftS[cb + 0], ACT);
                v.y = act_f(v.y * scaleS[cb + 1] + shiftS[cb + 1], ACT);
                v.z = act_f(v.z * scaleS[cb + 2] + shiftS[cb + 2], ACT);
                v.w = act_f(v.w * scaleS[cb + 3] + shiftS[cb + 3], ACT);
            }
            split_sts(aH, aL, row, c4, v);
        }
#pragma unroll
        for (int i = 0; i < 2; i++) {
            int f = tid + i * T;
            int row = f >> 3, c4 = f & 7;
            split_sts(bH, bL, row, c4, bReg[i]);
        }
    };
    auto mma_chunk = [&](int buf) {
        const uint16_t* aHp = AsH + buf * TSA;
        const uint16_t* aLp = AsL + buf * TSA;
        const uint16_t* bHp = BsH + buf * TSB;
        const uint16_t* bLp = BsL + buf * TSB;
#pragma unroll
        for (int ks = 0; ks < 2; ++ks) {
            const int k16 = ks * 16;          // bf16-unit col offset
            uint32_t ah[2][4], al[2][4], bh[4][2], bl[4][2];
#pragma unroll
            for (int ma = 0; ma < 2; ma++) {
                int r = wm * 32 + ma * 16 + g;
                ah[ma][0] = *(const uint32_t*)(aHp + r * LD + k16 + 2 * t);
                ah[ma][1] = *(const uint32_t*)(aHp + (r + 8) * LD + k16 + 2 * t);
                ah[ma][2] = *(const uint32_t*)(aHp + r * LD + k16 + 2 * t + 8);
                ah[ma][3] = *(const uint32_t*)(aHp + (r + 8) * LD + k16 + 2 * t + 8);
                al[ma][0] = *(const uint32_t*)(aLp + r * LD + k16 + 2 * t);
                al[ma][1] = *(const uint32_t*)(aLp + (r + 8) * LD + k16 + 2 * t);
                al[ma][2] = *(const uint32_t*)(aLp + r * LD + k16 + 2 * t + 8);
                al[ma][3] = *(const uint32_t*)(aLp + (r + 8) * LD + k16 + 2 * t + 8);
            }
#pragma unroll
            for (int nb = 0; nb < 4; nb++) {
                int n = wn * 32 + nb * 8 + g;
                bh[nb][0] = *(const uint32_t*)(bHp + n * LD + k16 + 2 * t);
                bh[nb][1] = *(const uint32_t*)(bHp + n * LD + k16 + 2 * t + 8);
                bl[nb][0] = *(const uint32_t*)(bLp + n * LD + k16 + 2 * t);
                bl[nb][1] = *(const uint32_t*)(bLp + n * LD + k16 + 2 * t + 8);
            }
#pragma unroll
            for (int ma = 0; ma < 2; ma++)
#pragma unroll
                for (int nb = 0; nb < 4; nb++) {
                    mma_bf16(c[ma][nb], ah[ma], bh[nb]);
                    mma_bf16(c[ma][nb], al[ma], bh[nb]);
                    mma_bf16(c[ma][nb], ah[ma], bl[nb]);
                }
        }
    };

    const int NT = K >> 5;
    ldg_tile(0);
    __syncthreads();          // scaleS/shiftS visible before sts(0)
    sts_tile(0, 0);
    for (int kt = 0; kt < NT; ++kt) {
        if (kt + 1 < NT) ldg_tile(kt + 1);   // LDGs in flight over barrier+MMA
        __syncthreads();                     // buf(kt) fully stored by all warps
        mma_chunk(kt & 1);
        if (kt + 1 < NT) sts_tile(kt + 1, (kt + 1) & 1);  // other buffer
    }

    // epilogue: optional row scaling by dinv, store, optional fused col stats
#pragma unroll
    for (int ma = 0; ma < 2; ma++) {
        int r0 = m0 + wm * 32 + ma * 16 + g;
        float d0 = 1.f, d1 = 1.f;
        if (SCALE) {
            if (r0 < M) d0 = g_dinv[r0];
            if (r0 + 8 < M) d1 = g_dinv[r0 + 8];
        }
#pragma unroll
        for (int nb = 0; nb < 4; nb++) {
            int col = wn * 32 + nb * 8 + 2 * t;
            if (SCALE) {
                c[ma][nb][0] *= d0; c[ma][nb][1] *= d0;
                c[ma][nb][2] *= d1; c[ma][nb][3] *= d1;
            }
            if (r0 < M)
                *(float2*)(C + (size_t)r0 * BN + col) =
                    make_float2(c[ma][nb][0], c[ma][nb][1]);
            if (r0 + 8 < M)
                *(float2*)(C + (size_t)(r0 + 8) * BN + col) =
                    make_float2(c[ma][nb][2], c[ma][nb][3]);
        }
    }

    if (STATS) {
        float ps[4][2], pq[4][2];
#pragma unroll
        for (int nb = 0; nb < 4; nb++)
            ps[nb][0] = ps[nb][1] = pq[nb][0] = pq[nb][1] = 0.f;
#pragma unroll
        for (int ma = 0; ma < 2; ma++) {
            int r0 = m0 + wm * 32 + ma * 16 + g;
#pragma unroll
            for (int nb = 0; nb < 4; nb++) {
                if (r0 < M) {
                    ps[nb][0] += c[ma][nb][0]; pq[nb][0] += c[ma][nb][0] * c[ma][nb][0];
                    ps[nb][1] += c[ma][nb][1]; pq[nb][1] += c[ma][nb][1] * c[ma][nb][1];
                }
                if (r0 + 8 < M) {
                    ps[nb][0] += c[ma][nb][2]; pq[nb][0] += c[ma][nb][2] * c[ma][nb][2];
                    ps[nb][1] += c[ma][nb][3]; pq[nb][1] += c[ma][nb][3] * c[ma][nb][3];
                }
            }
        }
        // reduce over g (lane bits 2..4): lanes sharing t hold identical columns
#pragma unroll
        for (int off = 4; off <= 16; off <<= 1)
#pragma unroll
            for (int nb = 0; nb < 4; nb++)
#pragma unroll
                for (int j = 0; j < 2; j++) {
                    ps[nb][j] += __shfl_xor_sync(0xffffffffu, ps[nb][j], off);
                    pq[nb][j] += __shfl_xor_sync(0xffffffffu, pq[nb][j], off);
                }
        if (lane < 4) {
#pragma unroll
            for (int nb = 0; nb < 4; nb++)
#pragma unroll
                for (int j = 0; j < 2; j++) {
                    int col = wn * 32 + nb * 8 + 2 * t + j;
                    atomicAdd(&sumo[col], ps[nb][j]);
                    atomicAdd(&sqo[col], pq[nb][j]);
                }
        }
    }
}

static constexpr int smem_mma(int bn, bool fuse) {
    return (4 * 128 + 4 * bn) * 40 * 2 + (fuse ? 1024 : 0);
}

// ---------------- prep: zero stats + indeg + all 4 weight transposes ------
// NOTE: grid must cover max(N, 512*128) threads (N=100000 > 65536).
__global__ void prep_kernel(const float* __restrict__ W1, const float* __restrict__ W2,
                            const float* __restrict__ Wg1, const float* __restrict__ Wg2,
                            int N) {
    int i = blockIdx.x * blockDim.x + threadIdx.x;
    if (i < 1024) ((float*)g_stats)[i] = 0.f;
    if (i < N) g_indeg[i] = 0;
    if (i < 512 * 128) { int k = i / 128, n = i % 128; g_wt1[n * 512 + k] = W1[i]; }
    if (i < 128 * 64)  { int k = i / 64,  n = i % 64;  g_wt2[n * 128 + k] = W2[i]; }
    if (i < 64 * 64)   { int k = i / 64,  n = i % 64;  g_wt3[n * 64 + k]  = Wg1[i]; }
    if (i < 64 * 32)   { int k = i / 32,  n = i % 32;  g_wt4[n * 64 + k]  = Wg2[i]; }
}

// ---------------- final BN apply (inline finalize) -> d_out ---------------
template <int C>
__global__ void bn_out_kernel(const float* __restrict__ in, float* __restrict__ out,
                              int M, const float* __restrict__ sumv,
                              const float* __restrict__ sqv,
                              const float* __restrict__ gamma,
                              const float* __restrict__ beta, float eps, float invM) {
    __shared__ float sc[C], sh[C];
    if (threadIdx.x < C) {
        float mean = sumv[threadIdx.x] * invM;
        float var = sqv[threadIdx.x] * invM - mean * mean;
        float s = gamma[threadIdx.x] * rsqrtf(var + eps);
        sc[threadIdx.x] = s;
        sh[threadIdx.x] = beta[threadIdx.x] - mean * s;
    }
    __syncthreads();
    int total4 = M * C / 4;
    for (int idx = blockIdx.x * blockDim.x + threadIdx.x; idx < total4;
         idx += gridDim.x * blockDim.x) {
        float4 v = ((const float4*)in)[idx];
        int c = (idx * 4) & (C - 1);
        ((float4*)out)[idx] = make_float4(v.x * sc[c + 0] + sh[c + 0],
                                          v.y * sc[c + 1] + sh[c + 1],
                                          v.z * sc[c + 2] + sh[c + 2],
                                          v.w * sc[c + 3] + sh[c + 3]);
    }
}

// ---------------- graph structure: degrees + CSR build --------------------
__global__ void count_kernel(const int* __restrict__ ei, int E) {
    int e = blockIdx.x * blockDim.x + threadIdx.x;
    if (e < E) atomicAdd(&g_indeg[ei[E + e]], 1);
}
__global__ void scan1_kernel(int N) {
    __shared__ int sh[1024];
    int tid = threadIdx.x;
    int i = blockIdx.x * 1024 + tid;
    int v = (i < N) ? g_indeg[i] : 0;
    sh[tid] = v;
    __syncthreads();
    for (int off = 1; off < 1024; off <<= 1) {
        int t = (tid >= off) ? sh[tid - off] : 0;
        __syncthreads();
        sh[tid] += t;
        __syncthreads();
    }
    if (i < N) g_rowptr[i] = sh[tid] - v;  // block-local exclusive
    if (tid == 1023) g_bsums[blockIdx.x] = sh[1023];
}
__global__ void scan2_kernel(int nb) {
    __shared__ int sh[256];
    int tid = threadIdx.x;
    int v = (tid < nb) ? g_bsums[tid] : 0;
    sh[tid] = v;
    __syncthreads();
    for (int off = 1; off < 256; off <<= 1) {
        int t = (tid >= off) ? sh[tid - off] : 0;
        __syncthreads();
        sh[tid] += t;
        __syncthreads();
    }
    if (tid < nb) g_bsums[tid] = sh[tid] - v;  // exclusive block offsets
}
__global__ void scan3_kernel(int N, int E) {   // also computes dinv
    int i = blockIdx.x * blockDim.x + threadIdx.x;
    if (i < N) {
        int v = g_rowptr[i] + g_bsums[i >> 10];
        g_rowptr[i] = v;
        g_cursor[i] = v;
        g_dinv[i] = rsqrtf((float)(g_indeg[i] + 1));  // +1 self loop
    }
    if (i == 0) g_rowptr[N] = E;
}
__global__ void fill_kernel(const int* __restrict__ ei, int E) {
    int e = blockIdx.x * blockDim.x + threadIdx.x;
    if (e < E) {
        int s = ei[e], d = ei[E + e];
        int p = atomicAdd(&g_cursor[d], 1);
        g_csrc[p] = s;
    }
}

// ---------------- GCN aggregation (inputs pre-scaled by dinv[src]) --------
// out[n] = dinv[n] * sum_{s in nbr(n) U {n}} hws[s]; optional fused col stats.
// No early return: inactive warps must reach the block barriers.
template <int C, bool STATS>
__global__ void agg_kernel(const float* __restrict__ hws,
                           float* __restrict__ out, int N,
                           float* __restrict__ sumv, float* __restrict__ sqv) {
    __shared__ float ssum[C], ssq[C];
    int tid = threadIdx.x;
    if (STATS) {
        if (tid < C) { ssum[tid] = 0.f; ssq[tid] = 0.f; }
        __syncthreads();
    }
    int warp = (blockIdx.x * blockDim.x + tid) >> 5;
    int lane = tid & 31;
    bool active = warp < N;
    int n = active ? warp : 0;

    if (C == 64) {
        float a0 = 0.f, a1 = 0.f, dn = 0.f;
        if (active) {
            dn = g_dinv[n];
            float2 sv = *(const float2*)(hws + (size_t)n * 64 + lane * 2);
            a0 = sv.x; a1 = sv.y;
            int start = g_rowptr[n], end = g_rowptr[n + 1];
            for (int i = start; i < end; i += 32) {
                int m = end - i;
                if (m > 32) m = 32;
                int s = (lane < m) ? g_csrc[i + lane] : 0;
#pragma unroll 4
                for (int j = 0; j < m; ++j) {
                    int sj = __shfl_sync(0xffffffffu, s, j);
                    float2 v = *(const float2*)(hws + (size_t)sj * 64 + lane * 2);
                    a0 += v.x;
                    a1 += v.y;
                }
            }
            a0 *= dn; a1 *= dn;
            *(float2*)(out + (size_t)n * 64 + lane * 2) = make_float2(a0, a1);
        }
        if (STATS) {
            if (active) {
                atomicAdd(&ssum[2 * lane], a0);
                atomicAdd(&ssum[2 * lane + 1], a1);
                atomicAdd(&ssq[2 * lane], a0 * a0);
                atomicAdd(&ssq[2 * lane + 1], a1 * a1);
            }
            __syncthreads();
            if (tid < C) {
                atomicAdd(&sumv[tid], ssum[tid]);
                atomicAdd(&sqv[tid], ssq[tid]);
            }
        }
    } else {  // C == 32
        float a0 = 0.f;
        if (active) {
            float dn = g_dinv[n];
            a0 = hws[(size_t)n * 32 + lane];
            int start = g_rowptr[n], end = g_rowptr[n + 1];
            for (int i = start; i < end; i += 32) {
                int m = end - i;
                if (m > 32) m = 32;
                int s = (lane < m) ? g_csrc[i + lane] : 0;
#pragma unroll 4
                for (int j = 0; j < m; ++j) {
                    int sj = __shfl_sync(0xffffffffu, s, j);
                    a0 += hws[(size_t)sj * 32 + lane];
                }
            }
            a0 *= dn;
            out[(size_t)n * 32 + lane] = a0;
        }
        if (STATS) {
            if (active) {
                atomicAdd(&ssum[lane], a0);
                atomicAdd(&ssq[lane], a0 * a0);
            }
            __syncthreads();
            if (tid < C) {
                atomicAdd(&sumv[tid], ssum[tid]);
                atomicAdd(&sqv[tid], ssq[tid]);
            }
        }
    }
}

// ---------------- driver ---------------------------------------------------
extern "C" void kernel_launch(void* const* d_in, const int* in_sizes, int n_in,
                              void* d_out, int out_size) {
    const float* x   = (const float*)d_in[0];
    const int*   ei  = (const int*)d_in[1];
    const float* W1  = (const float*)d_in[2];
    const float* g1  = (const float*)d_in[4];
    const float* be1 = (const float*)d_in[5];
    const float* W2  = (const float*)d_in[6];
    const float* g2  = (const float*)d_in[8];
    const float* be2 = (const float*)d_in[9];
    const float* Wg1 = (const float*)d_in[10];
    const float* g3  = (const float*)d_in[12];
    const float* be3 = (const float*)d_in[13];
    const float* Wg2 = (const float*)d_in[14];
    const float* g4  = (const float*)d_in[16];
    const float* be4 = (const float*)d_in[17];
    // (all bias vectors are mathematically cancelled by batch-stat BN; skipped)

    const int N = in_sizes[0] / 512;
    const int E = in_sizes[1] / 2;
    const float invM = 1.f / (float)N;

    float *p_h1, *p_h2, *p_hw, *p_agg, *p_hw2, *p_agg2;
    float *p_wt1, *p_wt2, *p_wt3, *p_wt4, *p_st;
    cudaGetSymbolAddress((void**)&p_h1, g_h1);
    cudaGetSymbolAddress((void**)&p_h2, g_h2);
    cudaGetSymbolAddress((void**)&p_hw, g_hw);
    cudaGetSymbolAddress((void**)&p_agg, g_agg);
    cudaGetSymbolAddress((void**)&p_hw2, g_hw2);
    cudaGetSymbolAddress((void**)&p_agg2, g_agg2);
    cudaGetSymbolAddress((void**)&p_wt1, g_wt1);
    cudaGetSymbolAddress((void**)&p_wt2, g_wt2);
    cudaGetSymbolAddress((void**)&p_wt3, g_wt3);
    cudaGetSymbolAddress((void**)&p_wt4, g_wt4);
    cudaGetSymbolAddress((void**)&p_st, g_stats);
    float* s0 = p_st;        float* q0 = p_st + 128;
    float* s1 = p_st + 256;  float* q1 = p_st + 384;
    float* s2 = p_st + 512;  float* q2 = p_st + 640;
    float* s3 = p_st + 768;  float* q3 = p_st + 896;

    cudaFuncSetAttribute((void*)mma_gemm<128, 0, false, false, true>, cudaFuncAttributeMaxDynamicSharedMemorySize, smem_mma(128, false));
    cudaFuncSetAttribute((void*)mma_gemm<64, 1, true, false, true>,   cudaFuncAttributeMaxDynamicSharedMemorySize, smem_mma(64, true));
    cudaFuncSetAttribute((void*)mma_gemm<64, 1, true, true, false>,   cudaFuncAttributeMaxDynamicSharedMemorySize, smem_mma(64, true));
    cudaFuncSetAttribute((void*)mma_gemm<32, 2, true, true, false>,   cudaFuncAttributeMaxDynamicSharedMemorySize, smem_mma(32, true));

    const int nbN = (N + 255) / 256;
    const int nbE = (E + 255) / 256;
    const int nbScan = (N + 1023) / 1024;
    const int nbM = (N + 127) / 128;
    // prep must cover BOTH the N-element indeg zeroing and 512*128 transpose
    const int prepThreads = (N > 512 * 128) ? N : 512 * 128;
    const int nbPrep = (prepThreads + 255) / 256;

    // Fork-join: CSR chain runs concurrently with encoder GEMM1/GEMM2.
    cudaStream_t sG;
    cudaEvent_t evFork, evJoin;
    cudaStreamCreateWithFlags(&sG, cudaStreamNonBlocking);
    cudaEventCreateWithFlags(&evFork, cudaEventDisableTiming);
    cudaEventCreateWithFlags(&evJoin, cudaEventDisableTiming);

    // prep: zero stats + indeg + all weight transposes (one kernel, stream 0)
    prep_kernel<<<nbPrep, 256>>>(W1, W2, Wg1, Wg2, N);
    cudaEventRecord(evFork, 0);
    cudaStreamWaitEvent(sG, evFork, 0);

    // Graph structure on side stream (independent of encoder GEMMs)
    count_kernel<<<nbE, 256, 0, sG>>>(ei, E);
    scan1_kernel<<<nbScan, 1024, 0, sG>>>(N);
    scan2_kernel<<<1, 256, 0, sG>>>(nbScan);
    scan3_kernel<<<nbN, 256, 0, sG>>>(N, E);
    fill_kernel<<<nbE, 256, 0, sG>>>(ei, E);
    cudaEventRecord(evJoin, sG);

    // encoder_L1: Linear(512,128) + fused col stats; BN+ELU deferred to gemm2
    mma_gemm<128, 0, false, false, true><<<nbM, 512, smem_mma(128, false)>>>(
        x, p_wt1, p_h1, N, 512, nullptr, nullptr, nullptr, nullptr, 0.f, 0.f, s0, q0);

    // encoder_L2: A = ELU(BN(h1)) + fused col stats; BN+ELU of h2 -> gemm3
    mma_gemm<64, 1, true, false, true><<<nbM, 256, smem_mma(64, true)>>>(
        p_h1, p_wt2, p_h2, N, 128, s0, q0, g1, be1, 1e-3f, invM, s1, q1);

    // join: gc1 needs dinv (SCALE epilogue) and CSR (agg)
    cudaStreamWaitEvent(0, evJoin, 0);

    // gc1: (ELU(BN(h2)) @ Wg1) * dinv[row]; aggregate + fused col stats
    mma_gemm<64, 1, true, true, false><<<nbM, 256, smem_mma(64, true)>>>(
        p_h2, p_wt3, p_hw, N, 64, s1, q1, g2, be2, 1e-3f, invM, nullptr, nullptr);
    agg_kernel<64, true><<<(N * 32 + 255) / 256, 256>>>(p_hw, p_agg, N, s2, q2);

    // gc2: A = ReLU(BN(agg)), output * dinv[row]; aggregate + stats; BN -> d_out
    mma_gemm<32, 2, true, true, false><<<nbM, 128, smem_mma(32, true)>>>(
        p_agg, p_wt4, p_hw2, N, 64, s2, q2, g3, be3, 1e-5f, invM, nullptr, nullptr);
    agg_kernel<32, true><<<(N * 32 + 255) / 256, 256>>>(p_hw2, p_agg2, N, s3, q3);
    bn_out_kernel<32><<<512, 256>>>(p_agg2, (float*)d_out, N, s3, q3, g4, be4,
                                    1e-5f, invM);

    cudaEventDestroy(evFork);
    cudaEventDestroy(evJoin);
    cudaStreamDestroy(sG);
}